// round 9
// baseline (speedup 1.0000x reference)
#include <cuda_runtime.h>
#include <cuda_fp16.h>
#include <math.h>

// ---------------- problem constants ----------------
namespace {
constexpr int N   = 10000;
constexpr int E   = 160000;
constexpr int C   = 64;
constexpr int LM  = 9;
constexpr int CAP = 64;          // bucket capacity (max degree ~40 for Poisson(16))
constexpr float RMAX    = 5.0f;
constexpr float INV_AVG = 1.0f / 16.0f;
constexpr float S3      = 1.7320508f;
constexpr float PI_F    = 3.14159265358979f;
constexpr float PREF    = 0.63245553203f; // sqrt(2/RMAX)

constexpr int GR_GRID = 625;     // persistent gather grid (~1 wave @ 5 blk/SM)
constexpr int ER_GRID = 625;     // persistent edge_radial grid (2 tiles each)
constexpr int ER_TILES = E / 128;        // 1250
constexpr int GR_GROUPS = N / 4;         // 2500
}

// ---------------- device scratch (static, no allocation) ----------------
__device__ float  g_h [N * C];
__device__ float  g_h1[N * C];
__device__ float  g_sc[N * C];
__device__ float  g_q [N * C];
__device__ float4 g_u [E];                 // unit edge vector (x,y,z,-)
__device__ __half g_Rh[(size_t)E * C];
__device__ int    g_cnt[N];
__device__ int2   g_bkt[(size_t)N * CAP];  // (edge, sender) per receiver slot

// ---------------- kernels ----------------

// zero counters + output bins, embed h
__global__ void k_prep(const float* __restrict__ W_embed,
                       const int* __restrict__ types,
                       float* __restrict__ out, int out_size) {
    int i = blockIdx.x * blockDim.x + threadIdx.x;
    if (i < N * C) {
        int n = i >> 6, c = i & 63;
        g_h[i] = W_embed[types[n] * C + c];
    }
    if (i < N) g_cnt[i] = 0;
    if (i < out_size) out[i] = 0.0f;
}

// Persistent fused edge kernel: geometry (u + bucket scatter), radial basis,
// radial MLP R = silu(ef@W1+b)@W2 -> fp16. Weights staged in smem ONCE per
// block; each block processes ER_TILES/ER_GRID tiles of 128 edges.
__global__ __launch_bounds__(256) void k_edge_radial(
    const float* __restrict__ pos, const int* __restrict__ ei,
    const float* __restrict__ W1, const float* __restrict__ b1,
    const float* __restrict__ W2)
{
    __shared__ float sW1[8 * 64];
    __shared__ float sB[64];
    __shared__ float sW2[64 * 64];
    __shared__ float sEfT[8 * 128];     // [k][edge]
    __shared__ float sHidT[64 * 128];   // [hidden][edge]

    int tid = threadIdx.x;
    for (int i = tid; i < 512; i += 256) sW1[i] = W1[i];
    if (tid < 64) sB[tid] = b1[tid];
    for (int i = tid; i < 4096; i += 256) sW2[i] = W2[i];

    int el = tid & 127;
    int eg = tid & 15;   // edge group: 8 edges
    int g2 = tid >> 4;   // hidden/channel quad

    for (int tile = blockIdx.x; tile < ER_TILES; tile += ER_GRID) {
        int e0 = tile * 128;
        int e = e0 + el;
        __syncthreads();   // protect sEfT/sHidT reuse across tiles

        // geometry (computed redundantly by the 2 thread-slices; cheap)
        int s = ei[e];
        int r = ei[E + e];
        float dx = pos[r * 3 + 0] - pos[s * 3 + 0];
        float dy = pos[r * 3 + 1] - pos[s * 3 + 1];
        float dz = pos[r * 3 + 2] - pos[s * 3 + 2];
        float rr = sqrtf(dx * dx + dy * dy + dz * dz);
        float rinv = 1.0f / fmaxf(rr, 1e-9f);
        float x = dx * rinv, y = dy * rinv, z = dz * rinv;

        if (tid < 128) {
            g_u[e] = make_float4(x, y, z, 0.0f);
            int slot = atomicAdd(&g_cnt[r], 1);
            if (slot < CAP) g_bkt[(size_t)r * CAP + slot] = make_int2(e, s);
        }

        // radial basis: 2 thread-slices x 4 sines each
        {
            float xx = rr * (1.0f / RMAX);
            float env = 0.0f;
            if (xx < 1.0f) {
                float x2 = xx * xx, x3 = x2 * xx;
                float x6 = x3 * x3, x7 = x6 * xx, x8 = x7 * xx;
                env = 1.0f - 28.0f * x6 + 48.0f * x7 - 21.0f * x8;
            }
            float w = rr * (PI_F / RMAX);
            float pe = PREF * rinv * env;
            int j = tid >> 7;   // 0 or 1
#pragma unroll
            for (int m = 0; m < 4; m++)
                sEfT[(4 * j + m) * 128 + el] = pe * sinf((float)(4 * j + m + 1) * w);
        }
        __syncthreads();

        // GEMM1: hid[el][h] = silu(b[h] + sum_k ef[el][k]*W1[k][h])
        float acc[4][8];
#pragma unroll
        for (int hi = 0; hi < 4; hi++) {
            float b = sB[g2 * 4 + hi];
#pragma unroll
            for (int ej = 0; ej < 8; ej++) acc[hi][ej] = b;
        }
#pragma unroll
        for (int k = 0; k < 8; k++) {
            float4 ea = *(const float4*)&sEfT[k * 128 + eg * 8];
            float4 eb = *(const float4*)&sEfT[k * 128 + eg * 8 + 4];
            float4 w4 = *(const float4*)&sW1[k * 64 + g2 * 4];
            float ee[8] = {ea.x, ea.y, ea.z, ea.w, eb.x, eb.y, eb.z, eb.w};
            float ww[4] = {w4.x, w4.y, w4.z, w4.w};
#pragma unroll
            for (int hi = 0; hi < 4; hi++)
#pragma unroll
                for (int ej = 0; ej < 8; ej++)
                    acc[hi][ej] = fmaf(ww[hi], ee[ej], acc[hi][ej]);
        }
#pragma unroll
        for (int hi = 0; hi < 4; hi++)
#pragma unroll
            for (int ej = 0; ej < 8; ej++) {
                float a = acc[hi][ej];
                sHidT[(g2 * 4 + hi) * 128 + eg * 8 + ej] = a / (1.0f + expf(-a));
            }
        __syncthreads();

        // GEMM2: R[el][c] = sum_k hid[el][k]*W2[k][c]
#pragma unroll
        for (int ci = 0; ci < 4; ci++)
#pragma unroll
            for (int ej = 0; ej < 8; ej++) acc[ci][ej] = 0.0f;
#pragma unroll 8
        for (int k = 0; k < 64; k++) {
            float4 ha = *(const float4*)&sHidT[k * 128 + eg * 8];
            float4 hb = *(const float4*)&sHidT[k * 128 + eg * 8 + 4];
            float4 w4 = *(const float4*)&sW2[k * 64 + g2 * 4];
            float hh[8] = {ha.x, ha.y, ha.z, ha.w, hb.x, hb.y, hb.z, hb.w};
            float ww[4] = {w4.x, w4.y, w4.z, w4.w};
#pragma unroll
            for (int ci = 0; ci < 4; ci++)
#pragma unroll
                for (int ej = 0; ej < 8; ej++)
                    acc[ci][ej] = fmaf(ww[ci], hh[ej], acc[ci][ej]);
        }
#pragma unroll
        for (int ej = 0; ej < 8; ej++) {
            int ee = e0 + eg * 8 + ej;
            __half2 p0 = __floats2half2_rn(acc[0][ej], acc[1][ej]);
            __half2 p1 = __floats2half2_rn(acc[2][ej], acc[3][ej]);
            __half2* dst = (__half2*)&g_Rh[(size_t)ee * C + g2 * 4];
            dst[0] = p0;
            dst[1] = p1;
        }
    }
}

// h1 = h @ W_up, sc = h @ W_sc; 32 nodes/block, 128 threads, 4x4 blocking
__global__ __launch_bounds__(128) void k_linear(const float* __restrict__ Wup,
                                                const float* __restrict__ Wsc) {
    constexpr int TS = 36;
    __shared__ float sWu[64 * 64];
    __shared__ float sWs[64 * 64];
    __shared__ float sHT[64 * TS];

    int tid = threadIdx.x;
    int n0 = blockIdx.x * 32;
    for (int i = tid; i < 4096; i += 128) { sWu[i] = Wup[i]; sWs[i] = Wsc[i]; }
    for (int i = tid; i < 512; i += 128) {
        int nl = i >> 4, kq = i & 15;
        int n = n0 + nl;
        float4 v = (n < N) ? *(const float4*)&g_h[n * 64 + kq * 4]
                           : make_float4(0.f, 0.f, 0.f, 0.f);
        sHT[(kq * 4 + 0) * TS + nl] = v.x;
        sHT[(kq * 4 + 1) * TS + nl] = v.y;
        sHT[(kq * 4 + 2) * TS + nl] = v.z;
        sHT[(kq * 4 + 3) * TS + nl] = v.w;
    }
    __syncthreads();

    int ng = tid & 7;
    int cg = tid >> 3;
    float au[4][4], as_[4][4];
#pragma unroll
    for (int ci = 0; ci < 4; ci++)
#pragma unroll
        for (int nj = 0; nj < 4; nj++) { au[ci][nj] = 0.f; as_[ci][nj] = 0.f; }

#pragma unroll 8
    for (int k = 0; k < 64; k++) {
        float4 h4 = *(const float4*)&sHT[k * TS + ng * 4];
        float4 u4 = *(const float4*)&sWu[k * 64 + cg * 4];
        float4 s4 = *(const float4*)&sWs[k * 64 + cg * 4];
        float hh[4] = {h4.x, h4.y, h4.z, h4.w};
        float uu[4] = {u4.x, u4.y, u4.z, u4.w};
        float ss[4] = {s4.x, s4.y, s4.z, s4.w};
#pragma unroll
        for (int ci = 0; ci < 4; ci++)
#pragma unroll
            for (int nj = 0; nj < 4; nj++) {
                au[ci][nj]  = fmaf(uu[ci], hh[nj], au[ci][nj]);
                as_[ci][nj] = fmaf(ss[ci], hh[nj], as_[ci][nj]);
            }
    }
#pragma unroll
    for (int nj = 0; nj < 4; nj++) {
        int n = n0 + ng * 4 + nj;
        if (n < N) {
            *(float4*)&g_h1[n * 64 + cg * 4] =
                make_float4(au[0][nj], au[1][nj], au[2][nj], au[3][nj]);
            *(float4*)&g_sc[n * 64 + cg * 4] =
                make_float4(as_[0][nj], as_[1][nj], as_[2][nj], as_[3][nj]);
        }
    }
}

// Persistent gather: each block loops over node-groups (4 nodes, 2 warps/node,
// edge-interleaved, 2 ch/thread). Bucket preloaded to registers; addresses
// via shuffles; sh rebuilt from u.
__global__ __launch_bounds__(256) void k_gather() {
    __shared__ float sPart[4][LM][64];   // parity-1 warp partials

    int nl   = threadIdx.x >> 6;         // node slot in block (0..3)
    int p    = (threadIdx.x >> 5) & 1;   // parity warp: edges p, p+2, ...
    int lane = threadIdx.x & 31;

    for (int grp = blockIdx.x; grp < GR_GROUPS; grp += GR_GRID) {
        int n = grp * 4 + nl;
        int cnt = g_cnt[n];
        if (cnt > CAP) cnt = CAP;
        const int2* bkt = &g_bkt[(size_t)n * CAP];

        // preload bucket entries: lane i holds slots i and i+32
        int2 my0 = __ldg(&bkt[lane]);
        int2 my1 = __ldg(&bkt[lane + 32]);

        float acc0[LM], acc1[LM];
#pragma unroll
        for (int j = 0; j < LM; j++) { acc0[j] = 0.0f; acc1[j] = 0.0f; }

#pragma unroll 4
        for (int i = p; i < cnt; i += 2) {
            int src = i & 31;
            int ex = (i < 32) ? my0.x : my1.x;
            int sx = (i < 32) ? my0.y : my1.y;
            int e = __shfl_sync(0xffffffffu, ex, src);
            int s = __shfl_sync(0xffffffffu, sx, src);

            float4 u4 = __ldg(&g_u[e]);          // uniform broadcast, 16B
            float2 rv = __half22float2(*(const __half2*)&g_Rh[(size_t)e * C + 2 * lane]);
            float2 hv = *(const float2*)&g_h1[s * C + 2 * lane];

            float x = u4.x, y = u4.y, z = u4.z;
            float shv[LM] = {1.0f, x, y, z,
                             S3 * x * y, S3 * y * z,
                             0.5f * (3.0f * z * z - 1.0f), S3 * x * z,
                             0.5f * S3 * (x * x - y * y)};
            float t0 = rv.x * hv.x;
            float t1 = rv.y * hv.y;
#pragma unroll
            for (int j = 0; j < LM; j++) {
                acc0[j] = fmaf(shv[j], t0, acc0[j]);
                acc1[j] = fmaf(shv[j], t1, acc1[j]);
            }
        }

        if (p == 1) {
#pragma unroll
            for (int j = 0; j < LM; j++) {
                sPart[nl][j][2 * lane]     = acc0[j];
                sPart[nl][j][2 * lane + 1] = acc1[j];
            }
        }
        __syncthreads();
        if (p == 0) {
            float q0 = 0.0f, q1 = 0.0f;
#pragma unroll
            for (int j = 0; j < LM; j++) {
                float a0 = (acc0[j] + sPart[nl][j][2 * lane])     * INV_AVG;
                float a1 = (acc1[j] + sPart[nl][j][2 * lane + 1]) * INV_AVG;
                if (j == 0) { q0 = a0; q1 = a1; }
                q0 = fmaf(a0, a0, q0);
                q1 = fmaf(a1, a1, q1);
            }
            *(float2*)&g_q[n * C + 2 * lane] = make_float2(q0, q1);
        }
        __syncthreads();   // sPart reuse across groups
    }
}

// h = q @ W_prod + sc; node energy -> per-graph bins. 32 nodes/block.
__global__ __launch_bounds__(128) void k_update(const float* __restrict__ Wp,
                                                const float* __restrict__ wro,
                                                const int* __restrict__ batch,
                                                float* __restrict__ out) {
    constexpr int TS = 36;
    __shared__ float sWp[64 * 64];
    __shared__ float sQT[64 * TS];
    __shared__ float sE[32];

    int tid = threadIdx.x;
    int n0 = blockIdx.x * 32;
    for (int i = tid; i < 4096; i += 128) sWp[i] = Wp[i];
    if (tid < 32) sE[tid] = 0.0f;
    for (int i = tid; i < 512; i += 128) {
        int nl = i >> 4, kq = i & 15;
        int n = n0 + nl;
        float4 v = (n < N) ? *(const float4*)&g_q[n * 64 + kq * 4]
                           : make_float4(0.f, 0.f, 0.f, 0.f);
        sQT[(kq * 4 + 0) * TS + nl] = v.x;
        sQT[(kq * 4 + 1) * TS + nl] = v.y;
        sQT[(kq * 4 + 2) * TS + nl] = v.z;
        sQT[(kq * 4 + 3) * TS + nl] = v.w;
    }
    __syncthreads();

    int ng = tid & 7;
    int cg = tid >> 3;
    float acc[4][4];
#pragma unroll
    for (int ci = 0; ci < 4; ci++)
#pragma unroll
        for (int nj = 0; nj < 4; nj++) acc[ci][nj] = 0.f;

#pragma unroll 8
    for (int k = 0; k < 64; k++) {
        float4 q4 = *(const float4*)&sQT[k * TS + ng * 4];
        float4 w4 = *(const float4*)&sWp[k * 64 + cg * 4];
        float qq[4] = {q4.x, q4.y, q4.z, q4.w};
        float ww[4] = {w4.x, w4.y, w4.z, w4.w};
#pragma unroll
        for (int ci = 0; ci < 4; ci++)
#pragma unroll
            for (int nj = 0; nj < 4; nj++)
                acc[ci][nj] = fmaf(ww[ci], qq[nj], acc[ci][nj]);
    }

    float4 wr4 = *(const float4*)&wro[cg * 4];
    float wr[4] = {wr4.x, wr4.y, wr4.z, wr4.w};
#pragma unroll
    for (int nj = 0; nj < 4; nj++) {
        int n = n0 + ng * 4 + nj;
        if (n < N) {
            float4 sc4 = *(const float4*)&g_sc[n * 64 + cg * 4];
            float hn[4] = {acc[0][nj] + sc4.x, acc[1][nj] + sc4.y,
                           acc[2][nj] + sc4.z, acc[3][nj] + sc4.w};
            *(float4*)&g_h[n * 64 + cg * 4] =
                make_float4(hn[0], hn[1], hn[2], hn[3]);
            float p = hn[0] * wr[0] + hn[1] * wr[1] + hn[2] * wr[2] + hn[3] * wr[3];
            atomicAdd(&sE[ng * 4 + nj], p);
        }
    }
    __syncthreads();
    if (tid < 32) {
        int n = n0 + tid;
        if (n < N) atomicAdd(&out[batch[n]], sE[tid]);
    }
}

// ---------------- launcher ----------------
extern "C" void kernel_launch(void* const* d_in, const int* in_sizes, int n_in,
                              void* d_out, int out_size) {
    const float* pos     = (const float*)d_in[0];
    const float* W_embed = (const float*)d_in[1];
    const float* W_r1    = (const float*)d_in[2];
    const float* b_r1    = (const float*)d_in[3];
    const float* W_r2    = (const float*)d_in[4];
    const float* W_up    = (const float*)d_in[5];
    const float* W_sc    = (const float*)d_in[6];
    const float* W_prod  = (const float*)d_in[7];
    const float* w_ro    = (const float*)d_in[8];
    const int*   types   = (const int*)d_in[9];
    const int*   ei      = (const int*)d_in[10];
    const int*   batch   = (const int*)d_in[11];
    float* out = (float*)d_out;

    k_prep<<<(N * C + 255) / 256, 256>>>(W_embed, types, out, out_size);
    k_edge_radial<<<ER_GRID, 256>>>(pos, ei, W_r1, b_r1, W_r2);

    for (int l = 0; l < 2; l++) {
        k_linear<<<(N + 31) / 32, 128>>>(W_up + l * C * C, W_sc + l * C * C);
        k_gather<<<GR_GRID, 256>>>();
        k_update<<<(N + 31) / 32, 128>>>(W_prod + l * C * C, w_ro + l * C, batch, out);
    }
}

// round 10
// speedup vs baseline: 1.0260x; 1.0260x over previous
#include <cuda_runtime.h>
#include <cuda_fp16.h>
#include <math.h>

// ---------------- problem constants ----------------
namespace {
constexpr int N   = 10000;
constexpr int E   = 160000;
constexpr int C   = 64;
constexpr int LM  = 9;
constexpr int CAP = 64;          // bucket capacity (max degree ~40 for Poisson(16))
constexpr float RMAX    = 5.0f;
constexpr float INV_AVG = 1.0f / 16.0f;
constexpr float S3      = 1.7320508f;
constexpr float PI_F    = 3.14159265358979f;
constexpr float PREF    = 0.63245553203f; // sqrt(2/RMAX)
}

typedef unsigned long long u64;

// ---------------- packed f32x2 helpers (sm_103a) ----------------
__device__ __forceinline__ u64 pk(float lo, float hi) {
    u64 r; asm("mov.b64 %0, {%1, %2};" : "=l"(r) : "f"(lo), "f"(hi)); return r;
}
__device__ __forceinline__ u64 pk2(float v) { return pk(v, v); }
__device__ __forceinline__ float2 upk(u64 v) {
    float2 f; asm("mov.b64 {%0, %1}, %2;" : "=f"(f.x), "=f"(f.y) : "l"(v)); return f;
}
__device__ __forceinline__ void fma2(u64& d, u64 a, u64 b, u64 c) {
    asm("fma.rn.f32x2 %0, %1, %2, %3;" : "=l"(d) : "l"(a), "l"(b), "l"(c));
}
__device__ __forceinline__ u64 mul2(u64 a, u64 b) {
    u64 d; asm("mul.rn.f32x2 %0, %1, %2;" : "=l"(d) : "l"(a), "l"(b)); return d;
}

// ---------------- device scratch (static, no allocation) ----------------
__device__ float      g_h [N * C];
__device__ float      g_h1[N * C];
__device__ float      g_sc[N * C];
__device__ float      g_q [N * C];
__device__ ulonglong2 g_shp[(size_t)E * 5];   // per-edge sh, duplicated f32x2 pairs
__device__ __half     g_Rh[(size_t)E * C];
__device__ int        g_cnt[N];
__device__ int2       g_bkt[(size_t)N * CAP]; // (edge, sender) per receiver slot

// ---------------- kernels ----------------

// zero counters + output bins, embed h
__global__ void k_prep(const float* __restrict__ W_embed,
                       const int* __restrict__ types,
                       float* __restrict__ out, int out_size) {
    int i = blockIdx.x * blockDim.x + threadIdx.x;
    if (i < N * C) {
        int n = i >> 6, c = i & 63;
        g_h[i] = W_embed[types[n] * C + c];
    }
    if (i < N) g_cnt[i] = 0;
    if (i < out_size) out[i] = 0.0f;
}

// Fused: per-edge geometry (packed sh + bucket scatter), radial Bessel basis,
// radial MLP R = silu(ef@W1+b)@W2 stored fp16. 256 threads / 128 edges;
// register-blocked GEMMs using packed f32x2 FMA along the edge dimension.
__global__ __launch_bounds__(256) void k_edge_radial(
    const float* __restrict__ pos, const int* __restrict__ ei,
    const float* __restrict__ W1, const float* __restrict__ b1,
    const float* __restrict__ W2)
{
    __shared__ float sW1[8 * 64];
    __shared__ float sB[64];
    __shared__ float sW2[64 * 64];
    __shared__ float sEfT[8 * 128];     // [k][edge]
    __shared__ float sHidT[64 * 128];   // [hidden][edge]

    int tid = threadIdx.x;
    int e0 = blockIdx.x * 128;
    int el = tid & 127;
    int e = e0 + el;

    for (int i = tid; i < 512; i += 256) sW1[i] = W1[i];
    if (tid < 64) sB[tid] = b1[tid];
    for (int i = tid; i < 4096; i += 256) sW2[i] = W2[i];

    // geometry (computed redundantly by the 2 thread-slices; cheap)
    int s = ei[e];
    int r = ei[E + e];
    float dx = pos[r * 3 + 0] - pos[s * 3 + 0];
    float dy = pos[r * 3 + 1] - pos[s * 3 + 1];
    float dz = pos[r * 3 + 2] - pos[s * 3 + 2];
    float rr = sqrtf(dx * dx + dy * dy + dz * dz);
    float rinv = 1.0f / fmaxf(rr, 1e-9f);
    float x = dx * rinv, y = dy * rinv, z = dz * rinv;

    if (tid < 128) {
        ulonglong2* sp = &g_shp[(size_t)e * 5];
        sp[0] = make_ulonglong2(pk2(1.0f), pk2(x));
        sp[1] = make_ulonglong2(pk2(y), pk2(z));
        sp[2] = make_ulonglong2(pk2(S3 * x * y), pk2(S3 * y * z));
        sp[3] = make_ulonglong2(pk2(0.5f * (3.0f * z * z - 1.0f)), pk2(S3 * x * z));
        sp[4] = make_ulonglong2(pk2(0.5f * S3 * (x * x - y * y)), 0ull);
        int slot = atomicAdd(&g_cnt[r], 1);
        if (slot < CAP) g_bkt[(size_t)r * CAP + slot] = make_int2(e, s);
    }

    // radial basis: 2 thread-slices x 4 sines each
    {
        float xx = rr * (1.0f / RMAX);
        float env = 0.0f;
        if (xx < 1.0f) {
            float x2 = xx * xx, x3 = x2 * xx;
            float x6 = x3 * x3, x7 = x6 * xx, x8 = x7 * xx;
            env = 1.0f - 28.0f * x6 + 48.0f * x7 - 21.0f * x8;
        }
        float w = rr * (PI_F / RMAX);
        float pe = PREF * rinv * env;
        int j = tid >> 7;   // 0 or 1
#pragma unroll
        for (int m = 0; m < 4; m++)
            sEfT[(4 * j + m) * 128 + el] = pe * sinf((float)(4 * j + m + 1) * w);
    }
    __syncthreads();

    int eg = tid & 15;   // edge group: 8 edges (4 packed pairs)
    int g2 = tid >> 4;   // hidden/channel quad

    // GEMM1: hid[el][h] = silu(b[h] + sum_k ef[el][k]*W1[k][h])  (f32x2 over edges)
    u64 acc[4][4];
#pragma unroll
    for (int hi = 0; hi < 4; hi++) {
        u64 b2 = pk2(sB[g2 * 4 + hi]);
#pragma unroll
        for (int ep = 0; ep < 4; ep++) acc[hi][ep] = b2;
    }
#pragma unroll
    for (int k = 0; k < 8; k++) {
        const u64* epv = (const u64*)&sEfT[k * 128 + eg * 8];
        u64 ee[4] = {epv[0], epv[1], epv[2], epv[3]};
        float4 w4 = *(const float4*)&sW1[k * 64 + g2 * 4];
        u64 ww[4] = {pk2(w4.x), pk2(w4.y), pk2(w4.z), pk2(w4.w)};
#pragma unroll
        for (int hi = 0; hi < 4; hi++)
#pragma unroll
            for (int ep = 0; ep < 4; ep++)
                fma2(acc[hi][ep], ww[hi], ee[ep], acc[hi][ep]);
    }
#pragma unroll
    for (int hi = 0; hi < 4; hi++)
#pragma unroll
        for (int ep = 0; ep < 4; ep++) {
            float2 a = upk(acc[hi][ep]);
            float v0 = a.x / (1.0f + expf(-a.x));
            float v1 = a.y / (1.0f + expf(-a.y));
            sHidT[(g2 * 4 + hi) * 128 + eg * 8 + 2 * ep]     = v0;
            sHidT[(g2 * 4 + hi) * 128 + eg * 8 + 2 * ep + 1] = v1;
        }
    __syncthreads();

    // GEMM2: R[el][c] = sum_k hid[el][k]*W2[k][c]  (f32x2 over edges)
#pragma unroll
    for (int ci = 0; ci < 4; ci++)
#pragma unroll
        for (int ep = 0; ep < 4; ep++) acc[ci][ep] = 0ull;
#pragma unroll 8
    for (int k = 0; k < 64; k++) {
        const u64* hpv = (const u64*)&sHidT[k * 128 + eg * 8];
        u64 hh[4] = {hpv[0], hpv[1], hpv[2], hpv[3]};
        float4 w4 = *(const float4*)&sW2[k * 64 + g2 * 4];
        u64 ww[4] = {pk2(w4.x), pk2(w4.y), pk2(w4.z), pk2(w4.w)};
#pragma unroll
        for (int ci = 0; ci < 4; ci++)
#pragma unroll
            for (int ep = 0; ep < 4; ep++)
                fma2(acc[ci][ep], ww[ci], hh[ep], acc[ci][ep]);
    }
#pragma unroll
    for (int ep = 0; ep < 4; ep++) {
        float2 c0 = upk(acc[0][ep]);
        float2 c1 = upk(acc[1][ep]);
        float2 c2 = upk(acc[2][ep]);
        float2 c3 = upk(acc[3][ep]);
        int eA = e0 + eg * 8 + 2 * ep;
        __half2* dA = (__half2*)&g_Rh[(size_t)eA * C + g2 * 4];
        dA[0] = __floats2half2_rn(c0.x, c1.x);
        dA[1] = __floats2half2_rn(c2.x, c3.x);
        __half2* dB = (__half2*)&g_Rh[(size_t)(eA + 1) * C + g2 * 4];
        dB[0] = __floats2half2_rn(c0.y, c1.y);
        dB[1] = __floats2half2_rn(c2.y, c3.y);
    }
}

// h1 = h @ W_up, sc = h @ W_sc; 32 nodes/block, 128 threads, f32x2 over nodes
__global__ __launch_bounds__(128) void k_linear(const float* __restrict__ Wup,
                                                const float* __restrict__ Wsc) {
    constexpr int TS = 36;
    __shared__ float sWu[64 * 64];
    __shared__ float sWs[64 * 64];
    __shared__ float sHT[64 * TS];

    int tid = threadIdx.x;
    int n0 = blockIdx.x * 32;
    for (int i = tid; i < 4096; i += 128) { sWu[i] = Wup[i]; sWs[i] = Wsc[i]; }
    for (int i = tid; i < 512; i += 128) {
        int nl = i >> 4, kq = i & 15;
        int n = n0 + nl;
        float4 v = (n < N) ? *(const float4*)&g_h[n * 64 + kq * 4]
                           : make_float4(0.f, 0.f, 0.f, 0.f);
        sHT[(kq * 4 + 0) * TS + nl] = v.x;
        sHT[(kq * 4 + 1) * TS + nl] = v.y;
        sHT[(kq * 4 + 2) * TS + nl] = v.z;
        sHT[(kq * 4 + 3) * TS + nl] = v.w;
    }
    __syncthreads();

    int ng = tid & 7;    // node quad (4 nodes = 2 packed pairs)
    int cg = tid >> 3;
    u64 au[4][2], as_[4][2];
#pragma unroll
    for (int ci = 0; ci < 4; ci++)
#pragma unroll
        for (int np = 0; np < 2; np++) { au[ci][np] = 0ull; as_[ci][np] = 0ull; }

#pragma unroll 8
    for (int k = 0; k < 64; k++) {
        const u64* hp = (const u64*)&sHT[k * TS + ng * 4];
        u64 hh[2] = {hp[0], hp[1]};
        float4 u4 = *(const float4*)&sWu[k * 64 + cg * 4];
        float4 s4 = *(const float4*)&sWs[k * 64 + cg * 4];
        u64 uu[4] = {pk2(u4.x), pk2(u4.y), pk2(u4.z), pk2(u4.w)};
        u64 ss[4] = {pk2(s4.x), pk2(s4.y), pk2(s4.z), pk2(s4.w)};
#pragma unroll
        for (int ci = 0; ci < 4; ci++)
#pragma unroll
            for (int np = 0; np < 2; np++) {
                fma2(au[ci][np],  uu[ci], hh[np], au[ci][np]);
                fma2(as_[ci][np], ss[ci], hh[np], as_[ci][np]);
            }
    }
#pragma unroll
    for (int np = 0; np < 2; np++) {
        float2 u0 = upk(au[0][np]), u1 = upk(au[1][np]),
               u2 = upk(au[2][np]), u3 = upk(au[3][np]);
        float2 s0 = upk(as_[0][np]), s1 = upk(as_[1][np]),
               s2 = upk(as_[2][np]), s3 = upk(as_[3][np]);
        int nA = n0 + ng * 4 + 2 * np;
        if (nA < N) {
            *(float4*)&g_h1[nA * 64 + cg * 4] = make_float4(u0.x, u1.x, u2.x, u3.x);
            *(float4*)&g_sc[nA * 64 + cg * 4] = make_float4(s0.x, s1.x, s2.x, s3.x);
        }
        if (nA + 1 < N) {
            *(float4*)&g_h1[(nA + 1) * 64 + cg * 4] = make_float4(u0.y, u1.y, u2.y, u3.y);
            *(float4*)&g_sc[(nA + 1) * 64 + cg * 4] = make_float4(s0.y, s1.y, s2.y, s3.y);
        }
    }
}

// gather: 4 nodes/block, 2 warps/node (edge-interleaved), 2 ch/thread packed
// into f32x2. Bucket preloaded to registers; addresses via shuffles; sh read
// as pre-packed duplicated pairs (uniform broadcast loads).
__global__ __launch_bounds__(256) void k_gather() {
    __shared__ float sPart[4][LM][64];   // parity-1 warp partials

    int nl   = threadIdx.x >> 6;         // node slot in block (0..3)
    int n    = blockIdx.x * 4 + nl;
    int p    = (threadIdx.x >> 5) & 1;   // parity warp: edges p, p+2, ...
    int lane = threadIdx.x & 31;
    int cnt  = g_cnt[n];
    if (cnt > CAP) cnt = CAP;
    const int2* bkt = &g_bkt[(size_t)n * CAP];

    // preload bucket entries: lane i holds slots i and i+32
    int2 my0 = __ldg(&bkt[lane]);
    int2 my1 = __ldg(&bkt[lane + 32]);

    u64 acc[LM];
#pragma unroll
    for (int j = 0; j < LM; j++) acc[j] = 0ull;

#pragma unroll 4
    for (int i = p; i < cnt; i += 2) {
        int src = i & 31;
        int ex = (i < 32) ? my0.x : my1.x;
        int sx = (i < 32) ? my0.y : my1.y;
        int e = __shfl_sync(0xffffffffu, ex, src);
        int s = __shfl_sync(0xffffffffu, sx, src);

        const ulonglong2* sp = &g_shp[(size_t)e * 5];
        ulonglong2 q0 = __ldg(&sp[0]);       // uniform broadcast
        ulonglong2 q1 = __ldg(&sp[1]);
        ulonglong2 q2 = __ldg(&sp[2]);
        ulonglong2 q3 = __ldg(&sp[3]);
        u64 q8 = __ldg((const u64*)&sp[4]);

        float2 rf = __half22float2(*(const __half2*)&g_Rh[(size_t)e * C + 2 * lane]);
        u64 hv = *(const u64*)&g_h1[s * C + 2 * lane];   // float2 as packed
        u64 t = mul2(pk(rf.x, rf.y), hv);

        fma2(acc[0], q0.x, t, acc[0]);
        fma2(acc[1], q0.y, t, acc[1]);
        fma2(acc[2], q1.x, t, acc[2]);
        fma2(acc[3], q1.y, t, acc[3]);
        fma2(acc[4], q2.x, t, acc[4]);
        fma2(acc[5], q2.y, t, acc[5]);
        fma2(acc[6], q3.x, t, acc[6]);
        fma2(acc[7], q3.y, t, acc[7]);
        fma2(acc[8], q8,   t, acc[8]);
    }

    if (p == 1) {
#pragma unroll
        for (int j = 0; j < LM; j++) {
            float2 f = upk(acc[j]);
            sPart[nl][j][2 * lane]     = f.x;
            sPart[nl][j][2 * lane + 1] = f.y;
        }
    }
    __syncthreads();
    if (p == 0) {
        float q0 = 0.0f, q1 = 0.0f;
#pragma unroll
        for (int j = 0; j < LM; j++) {
            float2 f = upk(acc[j]);
            float a0 = (f.x + sPart[nl][j][2 * lane])     * INV_AVG;
            float a1 = (f.y + sPart[nl][j][2 * lane + 1]) * INV_AVG;
            if (j == 0) { q0 = a0; q1 = a1; }
            q0 = fmaf(a0, a0, q0);
            q1 = fmaf(a1, a1, q1);
        }
        *(float2*)&g_q[n * C + 2 * lane] = make_float2(q0, q1);
    }
}

// h = q @ W_prod + sc; node energy -> per-graph bins. 32 nodes/block, f32x2.
__global__ __launch_bounds__(128) void k_update(const float* __restrict__ Wp,
                                                const float* __restrict__ wro,
                                                const int* __restrict__ batch,
                                                float* __restrict__ out) {
    constexpr int TS = 36;
    __shared__ float sWp[64 * 64];
    __shared__ float sQT[64 * TS];
    __shared__ float sE[32];

    int tid = threadIdx.x;
    int n0 = blockIdx.x * 32;
    for (int i = tid; i < 4096; i += 128) sWp[i] = Wp[i];
    if (tid < 32) sE[tid] = 0.0f;
    for (int i = tid; i < 512; i += 128) {
        int nl = i >> 4, kq = i & 15;
        int n = n0 + nl;
        float4 v = (n < N) ? *(const float4*)&g_q[n * 64 + kq * 4]
                           : make_float4(0.f, 0.f, 0.f, 0.f);
        sQT[(kq * 4 + 0) * TS + nl] = v.x;
        sQT[(kq * 4 + 1) * TS + nl] = v.y;
        sQT[(kq * 4 + 2) * TS + nl] = v.z;
        sQT[(kq * 4 + 3) * TS + nl] = v.w;
    }
    __syncthreads();

    int ng = tid & 7;
    int cg = tid >> 3;
    u64 acc[4][2];
#pragma unroll
    for (int ci = 0; ci < 4; ci++)
#pragma unroll
        for (int np = 0; np < 2; np++) acc[ci][np] = 0ull;

#pragma unroll 8
    for (int k = 0; k < 64; k++) {
        const u64* qp = (const u64*)&sQT[k * TS + ng * 4];
        u64 qq[2] = {qp[0], qp[1]};
        float4 w4 = *(const float4*)&sWp[k * 64 + cg * 4];
        u64 ww[4] = {pk2(w4.x), pk2(w4.y), pk2(w4.z), pk2(w4.w)};
#pragma unroll
        for (int ci = 0; ci < 4; ci++)
#pragma unroll
            for (int np = 0; np < 2; np++)
                fma2(acc[ci][np], ww[ci], qq[np], acc[ci][np]);
    }

    float4 wr4 = *(const float4*)&wro[cg * 4];
    float wr[4] = {wr4.x, wr4.y, wr4.z, wr4.w};
#pragma unroll
    for (int np = 0; np < 2; np++) {
        float2 c0 = upk(acc[0][np]), c1 = upk(acc[1][np]),
               c2 = upk(acc[2][np]), c3 = upk(acc[3][np]);
        int nA = n0 + ng * 4 + 2 * np;
#pragma unroll
        for (int half = 0; half < 2; half++) {
            int nn = nA + half;
            if (nn < N) {
                float h0 = half ? c0.y : c0.x;
                float h1 = half ? c1.y : c1.x;
                float h2 = half ? c2.y : c2.x;
                float h3 = half ? c3.y : c3.x;
                float4 sc4 = *(const float4*)&g_sc[nn * 64 + cg * 4];
                h0 += sc4.x; h1 += sc4.y; h2 += sc4.z; h3 += sc4.w;
                *(float4*)&g_h[nn * 64 + cg * 4] = make_float4(h0, h1, h2, h3);
                float pp = h0 * wr[0] + h1 * wr[1] + h2 * wr[2] + h3 * wr[3];
                atomicAdd(&sE[ng * 4 + 2 * np + half], pp);
            }
        }
    }
    __syncthreads();
    if (tid < 32) {
        int n = n0 + tid;
        if (n < N) atomicAdd(&out[batch[n]], sE[tid]);
    }
}

// ---------------- launcher ----------------
extern "C" void kernel_launch(void* const* d_in, const int* in_sizes, int n_in,
                              void* d_out, int out_size) {
    const float* pos     = (const float*)d_in[0];
    const float* W_embed = (const float*)d_in[1];
    const float* W_r1    = (const float*)d_in[2];
    const float* b_r1    = (const float*)d_in[3];
    const float* W_r2    = (const float*)d_in[4];
    const float* W_up    = (const float*)d_in[5];
    const float* W_sc    = (const float*)d_in[6];
    const float* W_prod  = (const float*)d_in[7];
    const float* w_ro    = (const float*)d_in[8];
    const int*   types   = (const int*)d_in[9];
    const int*   ei      = (const int*)d_in[10];
    const int*   batch   = (const int*)d_in[11];
    float* out = (float*)d_out;

    k_prep<<<(N * C + 255) / 256, 256>>>(W_embed, types, out, out_size);
    k_edge_radial<<<E / 128, 256>>>(pos, ei, W_r1, b_r1, W_r2);

    for (int l = 0; l < 2; l++) {
        k_linear<<<(N + 31) / 32, 128>>>(W_up + l * C * C, W_sc + l * C * C);
        k_gather<<<N / 4, 256>>>();
        k_update<<<(N + 31) / 32, 128>>>(W_prod + l * C * C, w_ro + l * C, batch, out);
    }
}

// round 11
// speedup vs baseline: 1.2271x; 1.1960x over previous
#include <cuda_runtime.h>
#include <cuda_fp16.h>
#include <mma.h>
#include <math.h>

using namespace nvcuda;

// ---------------- problem constants ----------------
namespace {
constexpr int N   = 10000;
constexpr int E   = 160000;
constexpr int C   = 64;
constexpr int LM  = 9;
constexpr int CAP = 64;          // bucket capacity (max degree ~40 for Poisson(16))
constexpr float RMAX    = 5.0f;
constexpr float INV_AVG = 1.0f / 16.0f;
constexpr float S3      = 1.7320508f;
constexpr float PI_F    = 3.14159265358979f;
constexpr float PREF    = 0.63245553203f; // sqrt(2/RMAX)
}

// ---------------- device scratch (static, no allocation) ----------------
__device__ float  g_h [N * C];
__device__ float  g_h1[N * C];
__device__ float  g_sc[N * C];
__device__ float  g_q [N * C];
__device__ float4 g_u [E];                 // unit edge vector (x,y,z,-)
__device__ __half g_Rh[(size_t)E * C];
__device__ int    g_cnt[N];
__device__ int2   g_bkt[(size_t)N * CAP];  // (edge, sender) per receiver slot

// ---------------- kernels ----------------

// zero counters + output bins, embed h
__global__ void k_prep(const float* __restrict__ W_embed,
                       const int* __restrict__ types,
                       float* __restrict__ out, int out_size) {
    int i = blockIdx.x * blockDim.x + threadIdx.x;
    if (i < N * C) {
        int n = i >> 6, c = i & 63;
        g_h[i] = W_embed[types[n] * C + c];
    }
    if (i < N) g_cnt[i] = 0;
    if (i < out_size) out[i] = 0.0f;
}

// Fused edge kernel: geometry (u + bucket scatter), radial basis, radial MLP.
// GEMM1 (E x 8 x 64) scalar fp32; GEMM2 (E x 64 x 64) on TENSOR CORES:
// hid staged fp16 [edge][k], W2 fp16 [k][c], wmma 16x16x16 fp32 accumulate.
// 256 threads / 128 edges per block.
__global__ __launch_bounds__(256) void k_edge_radial(
    const float* __restrict__ pos, const int* __restrict__ ei,
    const float* __restrict__ W1, const float* __restrict__ b1,
    const float* __restrict__ W2)
{
    __shared__ float sW1[8 * 64];
    __shared__ float sB[64];
    __shared__ __align__(16) __half sW2h[64 * 72];    // [k][c], stride 72
    __shared__ __align__(16) __half sHidE[128 * 72];  // [edge][k], stride 72
    __shared__ __align__(16) union {
        float ef[8 * 128];            // [k][edge] radial basis (GEMM1 input)
        float outbuf[8][16][36];      // per-warp wmma staging (after GEMM1)
    } U;

    int tid = threadIdx.x;
    int lane = tid & 31;
    int w = tid >> 5;                 // warp id 0..7
    int e0 = blockIdx.x * 128;
    int el = tid & 127;
    int e = e0 + el;

    for (int i = tid; i < 512; i += 256) sW1[i] = W1[i];
    if (tid < 64) sB[tid] = b1[tid];
    for (int i = tid; i < 4096; i += 256)
        sW2h[(i >> 6) * 72 + (i & 63)] = __float2half(W2[i]);

    // geometry (computed redundantly by the 2 thread-slices; cheap)
    int s = ei[e];
    int r = ei[E + e];
    float dx = pos[r * 3 + 0] - pos[s * 3 + 0];
    float dy = pos[r * 3 + 1] - pos[s * 3 + 1];
    float dz = pos[r * 3 + 2] - pos[s * 3 + 2];
    float rr = sqrtf(dx * dx + dy * dy + dz * dz);
    float rinv = 1.0f / fmaxf(rr, 1e-9f);
    float x = dx * rinv, y = dy * rinv, z = dz * rinv;

    if (tid < 128) {
        g_u[e] = make_float4(x, y, z, 0.0f);
        int slot = atomicAdd(&g_cnt[r], 1);
        if (slot < CAP) g_bkt[(size_t)r * CAP + slot] = make_int2(e, s);
    }

    // radial basis: 2 thread-slices x 4 sines each -> U.ef [k][edge]
    {
        float xx = rr * (1.0f / RMAX);
        float env = 0.0f;
        if (xx < 1.0f) {
            float x2 = xx * xx, x3 = x2 * xx;
            float x6 = x3 * x3, x7 = x6 * xx, x8 = x7 * xx;
            env = 1.0f - 28.0f * x6 + 48.0f * x7 - 21.0f * x8;
        }
        float wq = rr * (PI_F / RMAX);
        float pe = PREF * rinv * env;
        int j = tid >> 7;   // 0 or 1
#pragma unroll
        for (int m = 0; m < 4; m++)
            U.ef[(4 * j + m) * 128 + el] = pe * sinf((float)(4 * j + m + 1) * wq);
    }
    __syncthreads();

    int eg = tid & 15;   // edge group: 8 edges
    int g2 = tid >> 4;   // hidden quad

    // GEMM1: hid[el][h] = silu(b[h] + sum_k ef[el][k]*W1[k][h]) -> fp16 [edge][k]
    {
        float acc[4][8];
#pragma unroll
        for (int hi = 0; hi < 4; hi++) {
            float b = sB[g2 * 4 + hi];
#pragma unroll
            for (int ej = 0; ej < 8; ej++) acc[hi][ej] = b;
        }
#pragma unroll
        for (int k = 0; k < 8; k++) {
            float4 ea = *(const float4*)&U.ef[k * 128 + eg * 8];
            float4 eb = *(const float4*)&U.ef[k * 128 + eg * 8 + 4];
            float4 w4 = *(const float4*)&sW1[k * 64 + g2 * 4];
            float ee[8] = {ea.x, ea.y, ea.z, ea.w, eb.x, eb.y, eb.z, eb.w};
            float ww[4] = {w4.x, w4.y, w4.z, w4.w};
#pragma unroll
            for (int hi = 0; hi < 4; hi++)
#pragma unroll
                for (int ej = 0; ej < 8; ej++)
                    acc[hi][ej] = fmaf(ww[hi], ee[ej], acc[hi][ej]);
        }
#pragma unroll
        for (int hi = 0; hi < 4; hi++)
#pragma unroll
            for (int ej = 0; ej < 8; ej++) {
                float a = acc[hi][ej];
                float v = a / (1.0f + expf(-a));
                sHidE[(eg * 8 + ej) * 72 + g2 * 4 + hi] = __float2half(v);
            }
    }
    __syncthreads();   // sHidE visible; U.ef reads complete (outbuf may overwrite)

    // GEMM2 on tensor cores: R[edge][c] = hid @ W2.
    // Warp w owns 16 edges (rows 16w..16w+15); N processed in 2 halves of 32.
    {
        wmma::fragment<wmma::matrix_a, 16, 16, 16, __half, wmma::row_major> fa[4];
#pragma unroll
        for (int kf = 0; kf < 4; kf++)
            wmma::load_matrix_sync(fa[kf], &sHidE[(w * 16) * 72 + kf * 16], 72);

#pragma unroll
        for (int nh = 0; nh < 2; nh++) {
            wmma::fragment<wmma::accumulator, 16, 16, 16, float> fc0, fc1;
            wmma::fill_fragment(fc0, 0.0f);
            wmma::fill_fragment(fc1, 0.0f);
#pragma unroll
            for (int kf = 0; kf < 4; kf++) {
                wmma::fragment<wmma::matrix_b, 16, 16, 16, __half, wmma::row_major> fb0, fb1;
                wmma::load_matrix_sync(fb0, &sW2h[kf * 16 * 72 + nh * 32], 72);
                wmma::load_matrix_sync(fb1, &sW2h[kf * 16 * 72 + nh * 32 + 16], 72);
                wmma::mma_sync(fc0, fa[kf], fb0, fc0);
                wmma::mma_sync(fc1, fa[kf], fb1, fc1);
            }
            wmma::store_matrix_sync(&U.outbuf[w][0][0],  fc0, 36, wmma::mem_row_major);
            wmma::store_matrix_sync(&U.outbuf[w][0][16], fc1, 36, wmma::mem_row_major);
            __syncwarp();

            // convert + store: lane -> (row, half-row)
            int rrow = lane >> 1;
            int hh = lane & 1;
            const float* rowp = &U.outbuf[w][rrow][hh * 16];
            int ee = e0 + w * 16 + rrow;
            __half2* dst = (__half2*)&g_Rh[(size_t)ee * C + nh * 32 + hh * 16];
#pragma unroll
            for (int j = 0; j < 8; j++)
                dst[j] = __floats2half2_rn(rowp[2 * j], rowp[2 * j + 1]);
            __syncwarp();   // outbuf reused by next nh pass
        }
    }
}

// h1 = h @ W_up, sc = h @ W_sc; 32 nodes/block, 128 threads, 4x4 blocking
__global__ __launch_bounds__(128) void k_linear(const float* __restrict__ Wup,
                                                const float* __restrict__ Wsc) {
    constexpr int TS = 36;
    __shared__ float sWu[64 * 64];
    __shared__ float sWs[64 * 64];
    __shared__ float sHT[64 * TS];

    int tid = threadIdx.x;
    int n0 = blockIdx.x * 32;
    for (int i = tid; i < 4096; i += 128) { sWu[i] = Wup[i]; sWs[i] = Wsc[i]; }
    for (int i = tid; i < 512; i += 128) {
        int nl = i >> 4, kq = i & 15;
        int n = n0 + nl;
        float4 v = (n < N) ? *(const float4*)&g_h[n * 64 + kq * 4]
                           : make_float4(0.f, 0.f, 0.f, 0.f);
        sHT[(kq * 4 + 0) * TS + nl] = v.x;
        sHT[(kq * 4 + 1) * TS + nl] = v.y;
        sHT[(kq * 4 + 2) * TS + nl] = v.z;
        sHT[(kq * 4 + 3) * TS + nl] = v.w;
    }
    __syncthreads();

    int ng = tid & 7;
    int cg = tid >> 3;
    float au[4][4], as_[4][4];
#pragma unroll
    for (int ci = 0; ci < 4; ci++)
#pragma unroll
        for (int nj = 0; nj < 4; nj++) { au[ci][nj] = 0.f; as_[ci][nj] = 0.f; }

#pragma unroll 8
    for (int k = 0; k < 64; k++) {
        float4 h4 = *(const float4*)&sHT[k * TS + ng * 4];
        float4 u4 = *(const float4*)&sWu[k * 64 + cg * 4];
        float4 s4 = *(const float4*)&sWs[k * 64 + cg * 4];
        float hh[4] = {h4.x, h4.y, h4.z, h4.w};
        float uu[4] = {u4.x, u4.y, u4.z, u4.w};
        float ss[4] = {s4.x, s4.y, s4.z, s4.w};
#pragma unroll
        for (int ci = 0; ci < 4; ci++)
#pragma unroll
            for (int nj = 0; nj < 4; nj++) {
                au[ci][nj]  = fmaf(uu[ci], hh[nj], au[ci][nj]);
                as_[ci][nj] = fmaf(ss[ci], hh[nj], as_[ci][nj]);
            }
    }
#pragma unroll
    for (int nj = 0; nj < 4; nj++) {
        int n = n0 + ng * 4 + nj;
        if (n < N) {
            *(float4*)&g_h1[n * 64 + cg * 4] =
                make_float4(au[0][nj], au[1][nj], au[2][nj], au[3][nj]);
            *(float4*)&g_sc[n * 64 + cg * 4] =
                make_float4(as_[0][nj], as_[1][nj], as_[2][nj], as_[3][nj]);
        }
    }
}

// gather: 4 nodes/block, 2 warps per node (edge-interleaved), 2 ch/thread.
// Bucket preloaded to registers; addresses via shuffles; sh rebuilt from u.
__global__ __launch_bounds__(256) void k_gather() {
    __shared__ float sPart[4][LM][64];   // parity-1 warp partials

    int nl   = threadIdx.x >> 6;         // node slot in block (0..3)
    int n    = blockIdx.x * 4 + nl;
    int p    = (threadIdx.x >> 5) & 1;   // parity warp: edges p, p+2, ...
    int lane = threadIdx.x & 31;
    int cnt  = g_cnt[n];
    if (cnt > CAP) cnt = CAP;
    const int2* bkt = &g_bkt[(size_t)n * CAP];

    // preload bucket entries: lane i holds slots i and i+32
    int2 my0 = __ldg(&bkt[lane]);
    int2 my1 = __ldg(&bkt[lane + 32]);

    float acc0[LM], acc1[LM];
#pragma unroll
    for (int j = 0; j < LM; j++) { acc0[j] = 0.0f; acc1[j] = 0.0f; }

#pragma unroll 4
    for (int i = p; i < cnt; i += 2) {
        int src = i & 31;
        int ex = (i < 32) ? my0.x : my1.x;
        int sx = (i < 32) ? my0.y : my1.y;
        int e = __shfl_sync(0xffffffffu, ex, src);
        int s = __shfl_sync(0xffffffffu, sx, src);

        float4 u4 = __ldg(&g_u[e]);          // uniform broadcast, 16B
        float2 rv = __half22float2(*(const __half2*)&g_Rh[(size_t)e * C + 2 * lane]);
        float2 hv = *(const float2*)&g_h1[s * C + 2 * lane];

        float x = u4.x, y = u4.y, z = u4.z;
        float shv[LM] = {1.0f, x, y, z,
                         S3 * x * y, S3 * y * z,
                         0.5f * (3.0f * z * z - 1.0f), S3 * x * z,
                         0.5f * S3 * (x * x - y * y)};
        float t0 = rv.x * hv.x;
        float t1 = rv.y * hv.y;
#pragma unroll
        for (int j = 0; j < LM; j++) {
            acc0[j] = fmaf(shv[j], t0, acc0[j]);
            acc1[j] = fmaf(shv[j], t1, acc1[j]);
        }
    }

    if (p == 1) {
#pragma unroll
        for (int j = 0; j < LM; j++) {
            sPart[nl][j][2 * lane]     = acc0[j];
            sPart[nl][j][2 * lane + 1] = acc1[j];
        }
    }
    __syncthreads();
    if (p == 0) {
        float q0 = 0.0f, q1 = 0.0f;
#pragma unroll
        for (int j = 0; j < LM; j++) {
            float a0 = (acc0[j] + sPart[nl][j][2 * lane])     * INV_AVG;
            float a1 = (acc1[j] + sPart[nl][j][2 * lane + 1]) * INV_AVG;
            if (j == 0) { q0 = a0; q1 = a1; }
            q0 = fmaf(a0, a0, q0);
            q1 = fmaf(a1, a1, q1);
        }
        *(float2*)&g_q[n * C + 2 * lane] = make_float2(q0, q1);
    }
}

// h = q @ W_prod + sc; node energy -> per-graph bins. 32 nodes/block.
__global__ __launch_bounds__(128) void k_update(const float* __restrict__ Wp,
                                                const float* __restrict__ wro,
                                                const int* __restrict__ batch,
                                                float* __restrict__ out) {
    constexpr int TS = 36;
    __shared__ float sWp[64 * 64];
    __shared__ float sQT[64 * TS];
    __shared__ float sE[32];

    int tid = threadIdx.x;
    int n0 = blockIdx.x * 32;
    for (int i = tid; i < 4096; i += 128) sWp[i] = Wp[i];
    if (tid < 32) sE[tid] = 0.0f;
    for (int i = tid; i < 512; i += 128) {
        int nl = i >> 4, kq = i & 15;
        int n = n0 + nl;
        float4 v = (n < N) ? *(const float4*)&g_q[n * 64 + kq * 4]
                           : make_float4(0.f, 0.f, 0.f, 0.f);
        sQT[(kq * 4 + 0) * TS + nl] = v.x;
        sQT[(kq * 4 + 1) * TS + nl] = v.y;
        sQT[(kq * 4 + 2) * TS + nl] = v.z;
        sQT[(kq * 4 + 3) * TS + nl] = v.w;
    }
    __syncthreads();

    int ng = tid & 7;
    int cg = tid >> 3;
    float acc[4][4];
#pragma unroll
    for (int ci = 0; ci < 4; ci++)
#pragma unroll
        for (int nj = 0; nj < 4; nj++) acc[ci][nj] = 0.f;

#pragma unroll 8
    for (int k = 0; k < 64; k++) {
        float4 q4 = *(const float4*)&sQT[k * TS + ng * 4];
        float4 w4 = *(const float4*)&sWp[k * 64 + cg * 4];
        float qq[4] = {q4.x, q4.y, q4.z, q4.w};
        float ww[4] = {w4.x, w4.y, w4.z, w4.w};
#pragma unroll
        for (int ci = 0; ci < 4; ci++)
#pragma unroll
            for (int nj = 0; nj < 4; nj++)
                acc[ci][nj] = fmaf(ww[ci], qq[nj], acc[ci][nj]);
    }

    float4 wr4 = *(const float4*)&wro[cg * 4];
    float wr[4] = {wr4.x, wr4.y, wr4.z, wr4.w};
#pragma unroll
    for (int nj = 0; nj < 4; nj++) {
        int n = n0 + ng * 4 + nj;
        if (n < N) {
            float4 sc4 = *(const float4*)&g_sc[n * 64 + cg * 4];
            float hn[4] = {acc[0][nj] + sc4.x, acc[1][nj] + sc4.y,
                           acc[2][nj] + sc4.z, acc[3][nj] + sc4.w};
            *(float4*)&g_h[n * 64 + cg * 4] =
                make_float4(hn[0], hn[1], hn[2], hn[3]);
            float p = hn[0] * wr[0] + hn[1] * wr[1] + hn[2] * wr[2] + hn[3] * wr[3];
            atomicAdd(&sE[ng * 4 + nj], p);
        }
    }
    __syncthreads();
    if (tid < 32) {
        int n = n0 + tid;
        if (n < N) atomicAdd(&out[batch[n]], sE[tid]);
    }
}

// ---------------- launcher ----------------
extern "C" void kernel_launch(void* const* d_in, const int* in_sizes, int n_in,
                              void* d_out, int out_size) {
    const float* pos     = (const float*)d_in[0];
    const float* W_embed = (const float*)d_in[1];
    const float* W_r1    = (const float*)d_in[2];
    const float* b_r1    = (const float*)d_in[3];
    const float* W_r2    = (const float*)d_in[4];
    const float* W_up    = (const float*)d_in[5];
    const float* W_sc    = (const float*)d_in[6];
    const float* W_prod  = (const float*)d_in[7];
    const float* w_ro    = (const float*)d_in[8];
    const int*   types   = (const int*)d_in[9];
    const int*   ei      = (const int*)d_in[10];
    const int*   batch   = (const int*)d_in[11];
    float* out = (float*)d_out;

    k_prep<<<(N * C + 255) / 256, 256>>>(W_embed, types, out, out_size);
    k_edge_radial<<<E / 128, 256>>>(pos, ei, W_r1, b_r1, W_r2);

    for (int l = 0; l < 2; l++) {
        k_linear<<<(N + 31) / 32, 128>>>(W_up + l * C * C, W_sc + l * C * C);
        k_gather<<<N / 4, 256>>>();
        k_update<<<(N + 31) / 32, 128>>>(W_prod + l * C * C, w_ro + l * C, batch, out);
    }
}

// round 12
// speedup vs baseline: 1.2800x; 1.0432x over previous
#include <cuda_runtime.h>
#include <cuda_fp16.h>
#include <mma.h>
#include <math.h>

using namespace nvcuda;

// ---------------- problem constants ----------------
namespace {
constexpr int N   = 10000;
constexpr int E   = 160000;
constexpr int C   = 64;
constexpr int LM  = 9;
constexpr int CAP = 64;          // bucket capacity (max degree ~40 for Poisson(16))
constexpr float RMAX    = 5.0f;
constexpr float INV_AVG = 1.0f / 16.0f;
constexpr float S3      = 1.7320508f;
constexpr float PI_F    = 3.14159265358979f;
constexpr float PREF    = 0.63245553203f; // sqrt(2/RMAX)
}

// ---------------- device scratch (static, no allocation) ----------------
__device__ float  g_h [N * C];
__device__ float  g_h1[N * C];
__device__ float  g_sc[N * C];
__device__ float  g_q [N * C];
__device__ float4 g_u [E];                 // unit edge vector (x,y,z,-)
__device__ __half g_Rh[(size_t)E * C];
__device__ int    g_cnt[N];
__device__ int2   g_bkt[(size_t)N * CAP];  // (edge, sender) per receiver slot

// ---------------- kernels ----------------

// zero counters + output bins, embed h
__global__ void k_prep(const float* __restrict__ W_embed,
                       const int* __restrict__ types,
                       float* __restrict__ out, int out_size) {
    int i = blockIdx.x * blockDim.x + threadIdx.x;
    if (i < N * C) {
        int n = i >> 6, c = i & 63;
        g_h[i] = W_embed[types[n] * C + c];
    }
    if (i < N) g_cnt[i] = 0;
    if (i < out_size) out[i] = 0.0f;
}

// Fused edge kernel: geometry (u + bucket scatter), radial basis, radial MLP.
// GEMM1 (E x 8 x 64) scalar fp32; GEMM2 (E x 64 x 64) on tensor cores.
__global__ __launch_bounds__(256) void k_edge_radial(
    const float* __restrict__ pos, const int* __restrict__ ei,
    const float* __restrict__ W1, const float* __restrict__ b1,
    const float* __restrict__ W2)
{
    __shared__ float sW1[8 * 64];
    __shared__ float sB[64];
    __shared__ __align__(16) __half sW2h[64 * 72];    // [k][c], stride 72
    __shared__ __align__(16) __half sHidE[128 * 72];  // [edge][k], stride 72
    __shared__ __align__(16) union {
        float ef[8 * 128];            // [k][edge] radial basis (GEMM1 input)
        float outbuf[8][16][36];      // per-warp wmma staging (after GEMM1)
    } U;

    int tid = threadIdx.x;
    int lane = tid & 31;
    int w = tid >> 5;                 // warp id 0..7
    int e0 = blockIdx.x * 128;
    int el = tid & 127;
    int e = e0 + el;

    for (int i = tid; i < 512; i += 256) sW1[i] = W1[i];
    if (tid < 64) sB[tid] = b1[tid];
    for (int i = tid; i < 4096; i += 256)
        sW2h[(i >> 6) * 72 + (i & 63)] = __float2half(W2[i]);

    // geometry (computed redundantly by the 2 thread-slices; cheap)
    int s = ei[e];
    int r = ei[E + e];
    float dx = pos[r * 3 + 0] - pos[s * 3 + 0];
    float dy = pos[r * 3 + 1] - pos[s * 3 + 1];
    float dz = pos[r * 3 + 2] - pos[s * 3 + 2];
    float rr = sqrtf(dx * dx + dy * dy + dz * dz);
    float rinv = 1.0f / fmaxf(rr, 1e-9f);
    float x = dx * rinv, y = dy * rinv, z = dz * rinv;

    if (tid < 128) {
        g_u[e] = make_float4(x, y, z, 0.0f);
        int slot = atomicAdd(&g_cnt[r], 1);
        if (slot < CAP) g_bkt[(size_t)r * CAP + slot] = make_int2(e, s);
    }

    // radial basis: 2 thread-slices x 4 sines each -> U.ef [k][edge]
    {
        float xx = rr * (1.0f / RMAX);
        float env = 0.0f;
        if (xx < 1.0f) {
            float x2 = xx * xx, x3 = x2 * xx;
            float x6 = x3 * x3, x7 = x6 * xx, x8 = x7 * xx;
            env = 1.0f - 28.0f * x6 + 48.0f * x7 - 21.0f * x8;
        }
        float wq = rr * (PI_F / RMAX);
        float pe = PREF * rinv * env;
        int j = tid >> 7;   // 0 or 1
#pragma unroll
        for (int m = 0; m < 4; m++)
            U.ef[(4 * j + m) * 128 + el] = pe * sinf((float)(4 * j + m + 1) * wq);
    }
    __syncthreads();

    int eg = tid & 15;   // edge group: 8 edges
    int g2 = tid >> 4;   // hidden quad

    // GEMM1: hid[el][h] = silu(b[h] + sum_k ef[el][k]*W1[k][h]) -> fp16 [edge][k]
    {
        float acc[4][8];
#pragma unroll
        for (int hi = 0; hi < 4; hi++) {
            float b = sB[g2 * 4 + hi];
#pragma unroll
            for (int ej = 0; ej < 8; ej++) acc[hi][ej] = b;
        }
#pragma unroll
        for (int k = 0; k < 8; k++) {
            float4 ea = *(const float4*)&U.ef[k * 128 + eg * 8];
            float4 eb = *(const float4*)&U.ef[k * 128 + eg * 8 + 4];
            float4 w4 = *(const float4*)&sW1[k * 64 + g2 * 4];
            float ee[8] = {ea.x, ea.y, ea.z, ea.w, eb.x, eb.y, eb.z, eb.w};
            float ww[4] = {w4.x, w4.y, w4.z, w4.w};
#pragma unroll
            for (int hi = 0; hi < 4; hi++)
#pragma unroll
                for (int ej = 0; ej < 8; ej++)
                    acc[hi][ej] = fmaf(ww[hi], ee[ej], acc[hi][ej]);
        }
#pragma unroll
        for (int hi = 0; hi < 4; hi++)
#pragma unroll
            for (int ej = 0; ej < 8; ej++) {
                float a = acc[hi][ej];
                float v = a / (1.0f + expf(-a));
                sHidE[(eg * 8 + ej) * 72 + g2 * 4 + hi] = __float2half(v);
            }
    }
    __syncthreads();

    // GEMM2 on tensor cores: R[edge][c] = hid @ W2. Warp w owns 16 edges.
    {
        wmma::fragment<wmma::matrix_a, 16, 16, 16, __half, wmma::row_major> fa[4];
#pragma unroll
        for (int kf = 0; kf < 4; kf++)
            wmma::load_matrix_sync(fa[kf], &sHidE[(w * 16) * 72 + kf * 16], 72);

#pragma unroll
        for (int nh = 0; nh < 2; nh++) {
            wmma::fragment<wmma::accumulator, 16, 16, 16, float> fc0, fc1;
            wmma::fill_fragment(fc0, 0.0f);
            wmma::fill_fragment(fc1, 0.0f);
#pragma unroll
            for (int kf = 0; kf < 4; kf++) {
                wmma::fragment<wmma::matrix_b, 16, 16, 16, __half, wmma::row_major> fb0, fb1;
                wmma::load_matrix_sync(fb0, &sW2h[kf * 16 * 72 + nh * 32], 72);
                wmma::load_matrix_sync(fb1, &sW2h[kf * 16 * 72 + nh * 32 + 16], 72);
                wmma::mma_sync(fc0, fa[kf], fb0, fc0);
                wmma::mma_sync(fc1, fa[kf], fb1, fc1);
            }
            wmma::store_matrix_sync(&U.outbuf[w][0][0],  fc0, 36, wmma::mem_row_major);
            wmma::store_matrix_sync(&U.outbuf[w][0][16], fc1, 36, wmma::mem_row_major);
            __syncwarp();

            int rrow = lane >> 1;
            int hh = lane & 1;
            const float* rowp = &U.outbuf[w][rrow][hh * 16];
            int ee = e0 + w * 16 + rrow;
            __half2* dst = (__half2*)&g_Rh[(size_t)ee * C + nh * 32 + hh * 16];
#pragma unroll
            for (int j = 0; j < 8; j++)
                dst[j] = __floats2half2_rn(rowp[2 * j], rowp[2 * j + 1]);
            __syncwarp();
        }
    }
}

// h1 = h @ W_up, sc = h @ W_sc on tensor cores. 64 nodes/block, 4 warps,
// 16-node tiles (10000 = 625*16, tiles never straddle N).
__global__ __launch_bounds__(128) void k_linear(const float* __restrict__ Wup,
                                                const float* __restrict__ Wsc) {
    __shared__ __align__(16) __half sWu[64 * 72];
    __shared__ __align__(16) __half sWs[64 * 72];
    __shared__ __align__(16) __half sH [64 * 72];

    int tid = threadIdx.x;
    int w = tid >> 5;
    int n0 = blockIdx.x * 64;

    for (int i = tid; i < 4096; i += 128) {
        int k = i >> 6, c = i & 63;
        sWu[k * 72 + c] = __float2half(Wup[i]);
        sWs[k * 72 + c] = __float2half(Wsc[i]);
        int n = n0 + k;
        sH[k * 72 + c] = __float2half((n < N) ? g_h[n * 64 + c] : 0.0f);
    }
    __syncthreads();

    int nb = n0 + w * 16;
    if (nb < N) {
        wmma::fragment<wmma::matrix_a, 16, 16, 16, __half, wmma::row_major> fa[4];
#pragma unroll
        for (int kf = 0; kf < 4; kf++)
            wmma::load_matrix_sync(fa[kf], &sH[(w * 16) * 72 + kf * 16], 72);

#pragma unroll
        for (int nt = 0; nt < 4; nt++) {
            wmma::fragment<wmma::accumulator, 16, 16, 16, float> cu, cs;
            wmma::fill_fragment(cu, 0.0f);
            wmma::fill_fragment(cs, 0.0f);
#pragma unroll
            for (int kf = 0; kf < 4; kf++) {
                wmma::fragment<wmma::matrix_b, 16, 16, 16, __half, wmma::row_major> fu, fs;
                wmma::load_matrix_sync(fu, &sWu[kf * 16 * 72 + nt * 16], 72);
                wmma::load_matrix_sync(fs, &sWs[kf * 16 * 72 + nt * 16], 72);
                wmma::mma_sync(cu, fa[kf], fu, cu);
                wmma::mma_sync(cs, fa[kf], fs, cs);
            }
            wmma::store_matrix_sync(&g_h1[nb * 64 + nt * 16], cu, 64, wmma::mem_row_major);
            wmma::store_matrix_sync(&g_sc[nb * 64 + nt * 16], cs, 64, wmma::mem_row_major);
        }
    }
}

// gather: 4 nodes/block, 2 warps per node (edge-interleaved), 2 ch/thread.
// Bucket preloaded to registers; addresses via shuffles; sh rebuilt from u.
__global__ __launch_bounds__(256) void k_gather() {
    __shared__ float sPart[4][LM][64];   // parity-1 warp partials

    int nl   = threadIdx.x >> 6;         // node slot in block (0..3)
    int n    = blockIdx.x * 4 + nl;
    int p    = (threadIdx.x >> 5) & 1;   // parity warp: edges p, p+2, ...
    int lane = threadIdx.x & 31;
    int cnt  = g_cnt[n];
    if (cnt > CAP) cnt = CAP;
    const int2* bkt = &g_bkt[(size_t)n * CAP];

    // preload bucket entries: lane i holds slots i and i+32
    int2 my0 = __ldg(&bkt[lane]);
    int2 my1 = __ldg(&bkt[lane + 32]);

    float acc0[LM], acc1[LM];
#pragma unroll
    for (int j = 0; j < LM; j++) { acc0[j] = 0.0f; acc1[j] = 0.0f; }

#pragma unroll 4
    for (int i = p; i < cnt; i += 2) {
        int src = i & 31;
        int ex = (i < 32) ? my0.x : my1.x;
        int sx = (i < 32) ? my0.y : my1.y;
        int e = __shfl_sync(0xffffffffu, ex, src);
        int s = __shfl_sync(0xffffffffu, sx, src);

        float4 u4 = __ldg(&g_u[e]);          // uniform broadcast, 16B
        float2 rv = __half22float2(*(const __half2*)&g_Rh[(size_t)e * C + 2 * lane]);
        float2 hv = *(const float2*)&g_h1[s * C + 2 * lane];

        float x = u4.x, y = u4.y, z = u4.z;
        float shv[LM] = {1.0f, x, y, z,
                         S3 * x * y, S3 * y * z,
                         0.5f * (3.0f * z * z - 1.0f), S3 * x * z,
                         0.5f * S3 * (x * x - y * y)};
        float t0 = rv.x * hv.x;
        float t1 = rv.y * hv.y;
#pragma unroll
        for (int j = 0; j < LM; j++) {
            acc0[j] = fmaf(shv[j], t0, acc0[j]);
            acc1[j] = fmaf(shv[j], t1, acc1[j]);
        }
    }

    if (p == 1) {
#pragma unroll
        for (int j = 0; j < LM; j++) {
            sPart[nl][j][2 * lane]     = acc0[j];
            sPart[nl][j][2 * lane + 1] = acc1[j];
        }
    }
    __syncthreads();
    if (p == 0) {
        float q0 = 0.0f, q1 = 0.0f;
#pragma unroll
        for (int j = 0; j < LM; j++) {
            float a0 = (acc0[j] + sPart[nl][j][2 * lane])     * INV_AVG;
            float a1 = (acc1[j] + sPart[nl][j][2 * lane + 1]) * INV_AVG;
            if (j == 0) { q0 = a0; q1 = a1; }
            q0 = fmaf(a0, a0, q0);
            q1 = fmaf(a1, a1, q1);
        }
        *(float2*)&g_q[n * C + 2 * lane] = make_float2(q0, q1);
    }
}

// h = q @ W_prod + sc (tensor cores) ; node energy -> per-graph bins.
// 64 nodes/block, 4 warps, 16-node tiles.
__global__ __launch_bounds__(128) void k_update(const float* __restrict__ Wp,
                                                const float* __restrict__ wro,
                                                const int* __restrict__ batch,
                                                float* __restrict__ out) {
    __shared__ __align__(16) __half sWp[64 * 72];
    __shared__ __align__(16) __half sQ [64 * 72];
    __shared__ __align__(16) float sD[64 * 68];   // fp32 GEMM result, stride 68
    __shared__ float sWro[64];

    int tid = threadIdx.x;
    int w = tid >> 5;
    int n0 = blockIdx.x * 64;

    for (int i = tid; i < 4096; i += 128) {
        int k = i >> 6, c = i & 63;
        sWp[k * 72 + c] = __float2half(Wp[i]);
        int n = n0 + k;
        sQ[k * 72 + c] = __float2half((n < N) ? g_q[n * 64 + c] : 0.0f);
    }
    if (tid < 64) sWro[tid] = wro[tid];
    __syncthreads();

    int nb = n0 + w * 16;
    if (nb < N) {
        wmma::fragment<wmma::matrix_a, 16, 16, 16, __half, wmma::row_major> fa[4];
#pragma unroll
        for (int kf = 0; kf < 4; kf++)
            wmma::load_matrix_sync(fa[kf], &sQ[(w * 16) * 72 + kf * 16], 72);

#pragma unroll
        for (int nt = 0; nt < 4; nt++) {
            wmma::fragment<wmma::accumulator, 16, 16, 16, float> fc;
            wmma::fill_fragment(fc, 0.0f);
#pragma unroll
            for (int kf = 0; kf < 4; kf++) {
                wmma::fragment<wmma::matrix_b, 16, 16, 16, __half, wmma::row_major> fb;
                wmma::load_matrix_sync(fb, &sWp[kf * 16 * 72 + nt * 16], 72);
                wmma::mma_sync(fc, fa[kf], fb, fc);
            }
            wmma::store_matrix_sync(&sD[(w * 16) * 68 + nt * 16], fc, 68, wmma::mem_row_major);
        }
    }
    __syncthreads();

    // epilogue: 2 threads per node (32 ch each): h = D + sc, energy dot
    {
        int nl = tid >> 1;           // 0..63
        int hh = tid & 1;            // channel half
        int n = n0 + nl;
        float part = 0.0f;
        if (n < N) {
#pragma unroll
            for (int jq = 0; jq < 8; jq++) {
                int c = hh * 32 + jq * 4;
                float4 d4 = *(const float4*)&sD[nl * 68 + c];
                float4 s4 = *(const float4*)&g_sc[n * 64 + c];
                float4 hres = make_float4(d4.x + s4.x, d4.y + s4.y,
                                          d4.z + s4.z, d4.w + s4.w);
                *(float4*)&g_h[n * 64 + c] = hres;
                float4 w4 = *(const float4*)&sWro[c];
                part += hres.x * w4.x + hres.y * w4.y + hres.z * w4.z + hres.w * w4.w;
            }
        }
        part += __shfl_xor_sync(0xffffffffu, part, 1);
        if (hh == 0 && n < N) atomicAdd(&out[batch[n]], part);
    }
}

// ---------------- launcher ----------------
extern "C" void kernel_launch(void* const* d_in, const int* in_sizes, int n_in,
                              void* d_out, int out_size) {
    const float* pos     = (const float*)d_in[0];
    const float* W_embed = (const float*)d_in[1];
    const float* W_r1    = (const float*)d_in[2];
    const float* b_r1    = (const float*)d_in[3];
    const float* W_r2    = (const float*)d_in[4];
    const float* W_up    = (const float*)d_in[5];
    const float* W_sc    = (const float*)d_in[6];
    const float* W_prod  = (const float*)d_in[7];
    const float* w_ro    = (const float*)d_in[8];
    const int*   types   = (const int*)d_in[9];
    const int*   ei      = (const int*)d_in[10];
    const int*   batch   = (const int*)d_in[11];
    float* out = (float*)d_out;

    k_prep<<<(N * C + 255) / 256, 256>>>(W_embed, types, out, out_size);
    k_edge_radial<<<E / 128, 256>>>(pos, ei, W_r1, b_r1, W_r2);

    for (int l = 0; l < 2; l++) {
        k_linear<<<(N + 63) / 64, 128>>>(W_up + l * C * C, W_sc + l * C * C);
        k_gather<<<N / 4, 256>>>();
        k_update<<<(N + 63) / 64, 128>>>(W_prod + l * C * C, w_ro + l * C, batch, out);
    }
}

// round 13
// speedup vs baseline: 1.2854x; 1.0042x over previous
#include <cuda_runtime.h>
#include <cuda_fp16.h>
#include <mma.h>
#include <math.h>

using namespace nvcuda;

// ---------------- problem constants ----------------
namespace {
constexpr int N   = 10000;
constexpr int E   = 160000;
constexpr int C   = 64;
constexpr int LM  = 9;
constexpr int CAP = 64;          // bucket capacity (max degree ~40 for Poisson(16))
constexpr float RMAX    = 5.0f;
constexpr float INV_AVG = 1.0f / 16.0f;
constexpr float S3      = 1.7320508f;
constexpr float PI_F    = 3.14159265358979f;
constexpr float PREF    = 0.63245553203f; // sqrt(2/RMAX)
}

// ---------------- device scratch (static, no allocation) ----------------
__device__ float  g_h1[N * C];
__device__ float  g_sc[N * C];
__device__ float  g_q [N * C];
__device__ float4 g_u [E];                 // unit edge vector (x,y,z,-)
__device__ __half g_Rh[(size_t)E * C];
__device__ int    g_cnt[N];
__device__ int2   g_bkt[(size_t)N * CAP];  // (edge, sender) per receiver slot

// ---------------- kernels ----------------

// zero counters + output bins
__global__ void k_prep(float* __restrict__ out, int out_size) {
    int i = blockIdx.x * blockDim.x + threadIdx.x;
    if (i < N) g_cnt[i] = 0;
    if (i < out_size) out[i] = 0.0f;
}

// Fused edge kernel: geometry (u + bucket scatter), radial basis, radial MLP.
// GEMM1 (E x 8 x 64) scalar fp32; GEMM2 (E x 64 x 64) on tensor cores.
__global__ __launch_bounds__(256) void k_edge_radial(
    const float* __restrict__ pos, const int* __restrict__ ei,
    const float* __restrict__ W1, const float* __restrict__ b1,
    const float* __restrict__ W2)
{
    __shared__ float sW1[8 * 64];
    __shared__ float sB[64];
    __shared__ __align__(16) __half sW2h[64 * 72];    // [k][c], stride 72
    __shared__ __align__(16) __half sHidE[128 * 72];  // [edge][k], stride 72
    __shared__ __align__(16) union {
        float ef[8 * 128];            // [k][edge] radial basis (GEMM1 input)
        float outbuf[8][16][36];      // per-warp wmma staging (after GEMM1)
    } U;

    int tid = threadIdx.x;
    int lane = tid & 31;
    int w = tid >> 5;                 // warp id 0..7
    int e0 = blockIdx.x * 128;
    int el = tid & 127;
    int e = e0 + el;

    for (int i = tid; i < 512; i += 256) sW1[i] = W1[i];
    if (tid < 64) sB[tid] = b1[tid];
    for (int i = tid; i < 4096; i += 256)
        sW2h[(i >> 6) * 72 + (i & 63)] = __float2half(W2[i]);

    // geometry (computed redundantly by the 2 thread-slices; cheap)
    int s = ei[e];
    int r = ei[E + e];
    float dx = pos[r * 3 + 0] - pos[s * 3 + 0];
    float dy = pos[r * 3 + 1] - pos[s * 3 + 1];
    float dz = pos[r * 3 + 2] - pos[s * 3 + 2];
    float rr = sqrtf(dx * dx + dy * dy + dz * dz);
    float rinv = 1.0f / fmaxf(rr, 1e-9f);
    float x = dx * rinv, y = dy * rinv, z = dz * rinv;

    if (tid < 128) {
        g_u[e] = make_float4(x, y, z, 0.0f);
        int slot = atomicAdd(&g_cnt[r], 1);
        if (slot < CAP) g_bkt[(size_t)r * CAP + slot] = make_int2(e, s);
    }

    // radial basis: 2 thread-slices x 4 sines each -> U.ef [k][edge]
    {
        float xx = rr * (1.0f / RMAX);
        float env = 0.0f;
        if (xx < 1.0f) {
            float x2 = xx * xx, x3 = x2 * xx;
            float x6 = x3 * x3, x7 = x6 * xx, x8 = x7 * xx;
            env = 1.0f - 28.0f * x6 + 48.0f * x7 - 21.0f * x8;
        }
        float wq = rr * (PI_F / RMAX);
        float pe = PREF * rinv * env;
        int j = tid >> 7;   // 0 or 1
#pragma unroll
        for (int m = 0; m < 4; m++)
            U.ef[(4 * j + m) * 128 + el] = pe * sinf((float)(4 * j + m + 1) * wq);
    }
    __syncthreads();

    int eg = tid & 15;   // edge group: 8 edges
    int g2 = tid >> 4;   // hidden quad

    // GEMM1: hid[el][h] = silu(b[h] + sum_k ef[el][k]*W1[k][h]) -> fp16 [edge][k]
    {
        float acc[4][8];
#pragma unroll
        for (int hi = 0; hi < 4; hi++) {
            float b = sB[g2 * 4 + hi];
#pragma unroll
            for (int ej = 0; ej < 8; ej++) acc[hi][ej] = b;
        }
#pragma unroll
        for (int k = 0; k < 8; k++) {
            float4 ea = *(const float4*)&U.ef[k * 128 + eg * 8];
            float4 eb = *(const float4*)&U.ef[k * 128 + eg * 8 + 4];
            float4 w4 = *(const float4*)&sW1[k * 64 + g2 * 4];
            float ee[8] = {ea.x, ea.y, ea.z, ea.w, eb.x, eb.y, eb.z, eb.w};
            float ww[4] = {w4.x, w4.y, w4.z, w4.w};
#pragma unroll
            for (int hi = 0; hi < 4; hi++)
#pragma unroll
                for (int ej = 0; ej < 8; ej++)
                    acc[hi][ej] = fmaf(ww[hi], ee[ej], acc[hi][ej]);
        }
#pragma unroll
        for (int hi = 0; hi < 4; hi++)
#pragma unroll
            for (int ej = 0; ej < 8; ej++) {
                float a = acc[hi][ej];
                float v = a / (1.0f + expf(-a));
                sHidE[(eg * 8 + ej) * 72 + g2 * 4 + hi] = __float2half(v);
            }
    }
    __syncthreads();

    // GEMM2 on tensor cores: R[edge][c] = hid @ W2. Warp w owns 16 edges.
    {
        wmma::fragment<wmma::matrix_a, 16, 16, 16, __half, wmma::row_major> fa[4];
#pragma unroll
        for (int kf = 0; kf < 4; kf++)
            wmma::load_matrix_sync(fa[kf], &sHidE[(w * 16) * 72 + kf * 16], 72);

#pragma unroll
        for (int nh = 0; nh < 2; nh++) {
            wmma::fragment<wmma::accumulator, 16, 16, 16, float> fc0, fc1;
            wmma::fill_fragment(fc0, 0.0f);
            wmma::fill_fragment(fc1, 0.0f);
#pragma unroll
            for (int kf = 0; kf < 4; kf++) {
                wmma::fragment<wmma::matrix_b, 16, 16, 16, __half, wmma::row_major> fb0, fb1;
                wmma::load_matrix_sync(fb0, &sW2h[kf * 16 * 72 + nh * 32], 72);
                wmma::load_matrix_sync(fb1, &sW2h[kf * 16 * 72 + nh * 32 + 16], 72);
                wmma::mma_sync(fc0, fa[kf], fb0, fc0);
                wmma::mma_sync(fc1, fa[kf], fb1, fc1);
            }
            wmma::store_matrix_sync(&U.outbuf[w][0][0],  fc0, 36, wmma::mem_row_major);
            wmma::store_matrix_sync(&U.outbuf[w][0][16], fc1, 36, wmma::mem_row_major);
            __syncwarp();

            int rrow = lane >> 1;
            int hh = lane & 1;
            const float* rowp = &U.outbuf[w][rrow][hh * 16];
            int ee = e0 + w * 16 + rrow;
            __half2* dst = (__half2*)&g_Rh[(size_t)ee * C + nh * 32 + hh * 16];
#pragma unroll
            for (int j = 0; j < 8; j++)
                dst[j] = __floats2half2_rn(rowp[2 * j], rowp[2 * j + 1]);
            __syncwarp();
        }
    }
}

// layer-0 linear with fused embedding: h = W_embed[type], h1 = h@W_up, sc = h@W_sc.
// 64 nodes/block, 4 warps, 16-node tiles (10000 % 16 == 0).
__global__ __launch_bounds__(128) void k_linear0(
    const float* __restrict__ Wup, const float* __restrict__ Wsc,
    const float* __restrict__ W_embed, const int* __restrict__ types) {
    __shared__ __align__(16) __half sWu[64 * 72];
    __shared__ __align__(16) __half sWs[64 * 72];
    __shared__ __align__(16) __half sH [64 * 72];

    int tid = threadIdx.x;
    int w = tid >> 5;
    int n0 = blockIdx.x * 64;

    for (int i = tid; i < 4096; i += 128) {
        int k = i >> 6, c = i & 63;
        sWu[k * 72 + c] = __float2half(Wup[i]);
        sWs[k * 72 + c] = __float2half(Wsc[i]);
        int n = n0 + k;
        float hv = 0.0f;
        if (n < N) hv = W_embed[types[n] * 64 + c];
        sH[k * 72 + c] = __float2half(hv);
    }
    __syncthreads();

    int nb = n0 + w * 16;
    if (nb < N) {
        wmma::fragment<wmma::matrix_a, 16, 16, 16, __half, wmma::row_major> fa[4];
#pragma unroll
        for (int kf = 0; kf < 4; kf++)
            wmma::load_matrix_sync(fa[kf], &sH[(w * 16) * 72 + kf * 16], 72);

#pragma unroll
        for (int nt = 0; nt < 4; nt++) {
            wmma::fragment<wmma::accumulator, 16, 16, 16, float> cu, cs;
            wmma::fill_fragment(cu, 0.0f);
            wmma::fill_fragment(cs, 0.0f);
#pragma unroll
            for (int kf = 0; kf < 4; kf++) {
                wmma::fragment<wmma::matrix_b, 16, 16, 16, __half, wmma::row_major> fu, fs;
                wmma::load_matrix_sync(fu, &sWu[kf * 16 * 72 + nt * 16], 72);
                wmma::load_matrix_sync(fs, &sWs[kf * 16 * 72 + nt * 16], 72);
                wmma::mma_sync(cu, fa[kf], fu, cu);
                wmma::mma_sync(cs, fa[kf], fs, cs);
            }
            wmma::store_matrix_sync(&g_h1[nb * 64 + nt * 16], cu, 64, wmma::mem_row_major);
            wmma::store_matrix_sync(&g_sc[nb * 64 + nt * 16], cs, 64, wmma::mem_row_major);
        }
    }
}

// gather: 4 nodes/block, 2 warps per node (edge-interleaved), 2 ch/thread.
// Bucket preloaded to registers; addresses via shuffles; sh rebuilt from u.
// minBlocks=6 caps regs at 42 -> 75% theoretical occupancy (MLP is the wall).
__global__ __launch_bounds__(256, 6) void k_gather() {
    __shared__ float sPart[4][LM][64];   // parity-1 warp partials

    int nl   = threadIdx.x >> 6;         // node slot in block (0..3)
    int n    = blockIdx.x * 4 + nl;
    int p    = (threadIdx.x >> 5) & 1;   // parity warp: edges p, p+2, ...
    int lane = threadIdx.x & 31;
    int cnt  = g_cnt[n];
    if (cnt > CAP) cnt = CAP;
    const int2* bkt = &g_bkt[(size_t)n * CAP];

    // preload bucket entries: lane i holds slots i and i+32
    int2 my0 = __ldg(&bkt[lane]);
    int2 my1 = __ldg(&bkt[lane + 32]);

    float acc0[LM], acc1[LM];
#pragma unroll
    for (int j = 0; j < LM; j++) { acc0[j] = 0.0f; acc1[j] = 0.0f; }

#pragma unroll 4
    for (int i = p; i < cnt; i += 2) {
        int src = i & 31;
        int ex = (i < 32) ? my0.x : my1.x;
        int sx = (i < 32) ? my0.y : my1.y;
        int e = __shfl_sync(0xffffffffu, ex, src);
        int s = __shfl_sync(0xffffffffu, sx, src);

        float4 u4 = __ldg(&g_u[e]);          // uniform broadcast, 16B
        float2 rv = __half22float2(*(const __half2*)&g_Rh[(size_t)e * C + 2 * lane]);
        float2 hv = *(const float2*)&g_h1[s * C + 2 * lane];

        float x = u4.x, y = u4.y, z = u4.z;
        float shv[LM] = {1.0f, x, y, z,
                         S3 * x * y, S3 * y * z,
                         0.5f * (3.0f * z * z - 1.0f), S3 * x * z,
                         0.5f * S3 * (x * x - y * y)};
        float t0 = rv.x * hv.x;
        float t1 = rv.y * hv.y;
#pragma unroll
        for (int j = 0; j < LM; j++) {
            acc0[j] = fmaf(shv[j], t0, acc0[j]);
            acc1[j] = fmaf(shv[j], t1, acc1[j]);
        }
    }

    if (p == 1) {
#pragma unroll
        for (int j = 0; j < LM; j++) {
            sPart[nl][j][2 * lane]     = acc0[j];
            sPart[nl][j][2 * lane + 1] = acc1[j];
        }
    }
    __syncthreads();
    if (p == 0) {
        float q0 = 0.0f, q1 = 0.0f;
#pragma unroll
        for (int j = 0; j < LM; j++) {
            float a0 = (acc0[j] + sPart[nl][j][2 * lane])     * INV_AVG;
            float a1 = (acc1[j] + sPart[nl][j][2 * lane + 1]) * INV_AVG;
            if (j == 0) { q0 = a0; q1 = a1; }
            q0 = fmaf(a0, a0, q0);
            q1 = fmaf(a1, a1, q1);
        }
        *(float2*)&g_q[n * C + 2 * lane] = make_float2(q0, q1);
    }
}

// Fused update(+linear of next layer): h = q@W_prod + sc (tensor cores, h kept
// in SMEM only); energy dot -> per-graph bins; if DO_LIN, h1/sc for next layer
// computed in-block (h never touches gmem). 64 nodes/block, 8 warps.
template<bool DO_LIN>
__global__ __launch_bounds__(256) void k_upd(
    const float* __restrict__ Wp, const float* __restrict__ wro,
    const int* __restrict__ batch, float* __restrict__ out,
    const float* __restrict__ Wup, const float* __restrict__ Wsc)
{
    __shared__ __align__(16) __half sWp[64 * 72];
    __shared__ __align__(16) __half sQH[64 * 72];      // q (phase U), then h (phase L)
    __shared__ __align__(16) union {
        float D[64 * 68];                               // update GEMM result
        __half Wx[2 * 64 * 72];                         // then Wup|Wsc fp16
    } A;
    __shared__ __align__(16) float sWro[64];

    int tid = threadIdx.x;
    int w = tid >> 5;
    int n0 = blockIdx.x * 64;

    for (int i = tid; i < 4096; i += 256) {
        int k = i >> 6, c = i & 63;
        sWp[k * 72 + c] = __float2half(Wp[i]);
        int n = n0 + k;
        sQH[k * 72 + c] = __float2half((n < N) ? g_q[n * 64 + c] : 0.0f);
    }
    if (tid < 64) sWro[tid] = wro[tid];
    __syncthreads();

    // Phase U: D = q @ Wp. 16 tiles (4 rows x 4 cols) over 8 warps, 2 each.
#pragma unroll
    for (int t = 0; t < 2; t++) {
        int tile = w * 2 + t;
        int tr = tile >> 2, tc = tile & 3;
        if (n0 + tr * 16 < N) {
            wmma::fragment<wmma::accumulator, 16, 16, 16, float> fc;
            wmma::fill_fragment(fc, 0.0f);
#pragma unroll
            for (int kf = 0; kf < 4; kf++) {
                wmma::fragment<wmma::matrix_a, 16, 16, 16, __half, wmma::row_major> fa;
                wmma::fragment<wmma::matrix_b, 16, 16, 16, __half, wmma::row_major> fb;
                wmma::load_matrix_sync(fa, &sQH[(tr * 16) * 72 + kf * 16], 72);
                wmma::load_matrix_sync(fb, &sWp[(kf * 16) * 72 + tc * 16], 72);
                wmma::mma_sync(fc, fa, fb, fc);
            }
            wmma::store_matrix_sync(&A.D[(tr * 16) * 68 + tc * 16], fc, 68,
                                    wmma::mem_row_major);
        }
    }
    __syncthreads();

    // Epilogue: 4 threads/node, 16 ch each: h = D + sc; energy; h -> sQH fp16
    {
        int nl = tid >> 2, qh = tid & 3;
        int n = n0 + nl;
        float part = 0.0f;
        if (n < N) {
#pragma unroll
            for (int j = 0; j < 4; j++) {
                int c = qh * 16 + j * 4;
                float4 d4 = *(const float4*)&A.D[nl * 68 + c];
                float4 s4 = *(const float4*)&g_sc[n * 64 + c];
                float h0 = d4.x + s4.x, h1v = d4.y + s4.y;
                float h2 = d4.z + s4.z, h3 = d4.w + s4.w;
                float4 w4 = *(const float4*)&sWro[c];
                part += h0 * w4.x + h1v * w4.y + h2 * w4.z + h3 * w4.w;
                if (DO_LIN) {
                    *(__half2*)&sQH[nl * 72 + c]     = __floats2half2_rn(h0, h1v);
                    *(__half2*)&sQH[nl * 72 + c + 2] = __floats2half2_rn(h2, h3);
                }
            }
        }
        part += __shfl_xor_sync(0xffffffffu, part, 1);
        part += __shfl_xor_sync(0xffffffffu, part, 2);
        if ((tid & 3) == 0 && n < N) atomicAdd(&out[batch[n]], part);
    }

    if (DO_LIN) {
        __syncthreads();   // D fully consumed; sQH now holds h
        for (int i = tid; i < 4096; i += 256) {
            int k = i >> 6, c = i & 63;
            A.Wx[k * 72 + c]           = __float2half(Wup[i]);
            A.Wx[64 * 72 + k * 72 + c] = __float2half(Wsc[i]);
        }
        __syncthreads();

        // Phase L: h1 = h@Wup, sc = h@Wsc. warp w: row = w>>1, 2 col tiles.
        int tr = w >> 1;
        if (n0 + tr * 16 < N) {
            wmma::fragment<wmma::matrix_a, 16, 16, 16, __half, wmma::row_major> fa[4];
#pragma unroll
            for (int kf = 0; kf < 4; kf++)
                wmma::load_matrix_sync(fa[kf], &sQH[(tr * 16) * 72 + kf * 16], 72);
#pragma unroll
            for (int cc = 0; cc < 2; cc++) {
                int tc = (w & 1) * 2 + cc;
                wmma::fragment<wmma::accumulator, 16, 16, 16, float> cu, cs;
                wmma::fill_fragment(cu, 0.0f);
                wmma::fill_fragment(cs, 0.0f);
#pragma unroll
                for (int kf = 0; kf < 4; kf++) {
                    wmma::fragment<wmma::matrix_b, 16, 16, 16, __half, wmma::row_major> fu, fs;
                    wmma::load_matrix_sync(fu, &A.Wx[(kf * 16) * 72 + tc * 16], 72);
                    wmma::load_matrix_sync(fs, &A.Wx[64 * 72 + (kf * 16) * 72 + tc * 16], 72);
                    wmma::mma_sync(cu, fa[kf], fu, cu);
                    wmma::mma_sync(cs, fa[kf], fs, cs);
                }
                int nb = n0 + tr * 16;
                wmma::store_matrix_sync(&g_h1[nb * 64 + tc * 16], cu, 64, wmma::mem_row_major);
                wmma::store_matrix_sync(&g_sc[nb * 64 + tc * 16], cs, 64, wmma::mem_row_major);
            }
        }
    }
}

// ---------------- launcher ----------------
extern "C" void kernel_launch(void* const* d_in, const int* in_sizes, int n_in,
                              void* d_out, int out_size) {
    const float* pos     = (const float*)d_in[0];
    const float* W_embed = (const float*)d_in[1];
    const float* W_r1    = (const float*)d_in[2];
    const float* b_r1    = (const float*)d_in[3];
    const float* W_r2    = (const float*)d_in[4];
    const float* W_up    = (const float*)d_in[5];
    const float* W_sc    = (const float*)d_in[6];
    const float* W_prod  = (const float*)d_in[7];
    const float* w_ro    = (const float*)d_in[8];
    const int*   types   = (const int*)d_in[9];
    const int*   ei      = (const int*)d_in[10];
    const int*   batch   = (const int*)d_in[11];
    float* out = (float*)d_out;

    k_prep<<<(N + 255) / 256, 256>>>(out, out_size);
    k_edge_radial<<<E / 128, 256>>>(pos, ei, W_r1, b_r1, W_r2);
    k_linear0<<<(N + 63) / 64, 128>>>(W_up, W_sc, W_embed, types);

    k_gather<<<N / 4, 256>>>();
    k_upd<true><<<(N + 63) / 64, 256>>>(W_prod, w_ro, batch, out,
                                        W_up + C * C, W_sc + C * C);
    k_gather<<<N / 4, 256>>>();
    k_upd<false><<<(N + 63) / 64, 256>>>(W_prod + C * C, w_ro + C, batch, out,
                                         nullptr, nullptr);
}

// round 14
// speedup vs baseline: 1.3632x; 1.0605x over previous
#include <cuda_runtime.h>
#include <cuda_fp16.h>
#include <mma.h>
#include <math.h>

using namespace nvcuda;

// ---------------- problem constants ----------------
namespace {
constexpr int N   = 10000;
constexpr int E   = 160000;
constexpr int C   = 64;
constexpr int LM  = 9;
constexpr int CAP = 64;          // bucket capacity (max degree ~40 for Poisson(16))
constexpr float RMAX    = 5.0f;
constexpr float INV_AVG = 1.0f / 16.0f;
constexpr float S3      = 1.7320508f;
constexpr float PI_F    = 3.14159265358979f;
constexpr float PREF    = 0.63245553203f; // sqrt(2/RMAX)
}

// ---------------- device scratch (static, no allocation) ----------------
__device__ float  g_h1[N * C];
__device__ float  g_sc[N * C];
__device__ float  g_q [N * C];
__device__ float4 g_u [E];                 // unit edge vector (x,y,z,-)
__device__ __half g_Rh[(size_t)E * C];
__device__ int    g_cnt[N];
__device__ int2   g_bkt[(size_t)N * CAP];  // (edge, sender) per receiver slot

// ---------------- kernels ----------------

// zero counters + output bins
__global__ void k_prep(float* __restrict__ out, int out_size) {
    int i = blockIdx.x * blockDim.x + threadIdx.x;
    if (i < N) g_cnt[i] = 0;
    if (i < out_size) out[i] = 0.0f;
}

// Fused edge kernel: geometry (u + bucket scatter), radial basis, radial MLP.
// GEMM1 (E x 8 x 64) scalar fp32; GEMM2 (E x 64 x 64) on tensor cores.
__global__ __launch_bounds__(256) void k_edge_radial(
    const float* __restrict__ pos, const int* __restrict__ ei,
    const float* __restrict__ W1, const float* __restrict__ b1,
    const float* __restrict__ W2)
{
    __shared__ float sW1[8 * 64];
    __shared__ float sB[64];
    __shared__ __align__(16) __half sW2h[64 * 72];    // [k][c], stride 72
    __shared__ __align__(16) __half sHidE[128 * 72];  // [edge][k], stride 72
    __shared__ __align__(16) union {
        float ef[8 * 128];            // [k][edge] radial basis (GEMM1 input)
        float outbuf[8][16][36];      // per-warp wmma staging (after GEMM1)
    } U;

    int tid = threadIdx.x;
    int lane = tid & 31;
    int w = tid >> 5;                 // warp id 0..7
    int e0 = blockIdx.x * 128;
    int el = tid & 127;
    int e = e0 + el;

    for (int i = tid; i < 512; i += 256) sW1[i] = W1[i];
    if (tid < 64) sB[tid] = b1[tid];
    for (int i = tid; i < 4096; i += 256)
        sW2h[(i >> 6) * 72 + (i & 63)] = __float2half(W2[i]);

    // geometry (computed redundantly by the 2 thread-slices; cheap)
    int s = ei[e];
    int r = ei[E + e];
    float dx = pos[r * 3 + 0] - pos[s * 3 + 0];
    float dy = pos[r * 3 + 1] - pos[s * 3 + 1];
    float dz = pos[r * 3 + 2] - pos[s * 3 + 2];
    float rr = sqrtf(dx * dx + dy * dy + dz * dz);
    float rinv = 1.0f / fmaxf(rr, 1e-9f);
    float x = dx * rinv, y = dy * rinv, z = dz * rinv;

    if (tid < 128) {
        g_u[e] = make_float4(x, y, z, 0.0f);
        int slot = atomicAdd(&g_cnt[r], 1);
        if (slot < CAP) g_bkt[(size_t)r * CAP + slot] = make_int2(e, s);
    }

    // radial basis: 2 thread-slices x 4 sines each -> U.ef [k][edge]
    {
        float xx = rr * (1.0f / RMAX);
        float env = 0.0f;
        if (xx < 1.0f) {
            float x2 = xx * xx, x3 = x2 * xx;
            float x6 = x3 * x3, x7 = x6 * xx, x8 = x7 * xx;
            env = 1.0f - 28.0f * x6 + 48.0f * x7 - 21.0f * x8;
        }
        float wq = rr * (PI_F / RMAX);
        float pe = PREF * rinv * env;
        int j = tid >> 7;   // 0 or 1
#pragma unroll
        for (int m = 0; m < 4; m++)
            U.ef[(4 * j + m) * 128 + el] = pe * sinf((float)(4 * j + m + 1) * wq);
    }
    __syncthreads();

    int eg = tid & 15;   // edge group: 8 edges
    int g2 = tid >> 4;   // hidden quad

    // GEMM1: hid[el][h] = silu(b[h] + sum_k ef[el][k]*W1[k][h]) -> fp16 [edge][k]
    {
        float acc[4][8];
#pragma unroll
        for (int hi = 0; hi < 4; hi++) {
            float b = sB[g2 * 4 + hi];
#pragma unroll
            for (int ej = 0; ej < 8; ej++) acc[hi][ej] = b;
        }
#pragma unroll
        for (int k = 0; k < 8; k++) {
            float4 ea = *(const float4*)&U.ef[k * 128 + eg * 8];
            float4 eb = *(const float4*)&U.ef[k * 128 + eg * 8 + 4];
            float4 w4 = *(const float4*)&sW1[k * 64 + g2 * 4];
            float ee[8] = {ea.x, ea.y, ea.z, ea.w, eb.x, eb.y, eb.z, eb.w};
            float ww[4] = {w4.x, w4.y, w4.z, w4.w};
#pragma unroll
            for (int hi = 0; hi < 4; hi++)
#pragma unroll
                for (int ej = 0; ej < 8; ej++)
                    acc[hi][ej] = fmaf(ww[hi], ee[ej], acc[hi][ej]);
        }
#pragma unroll
        for (int hi = 0; hi < 4; hi++)
#pragma unroll
            for (int ej = 0; ej < 8; ej++) {
                float a = acc[hi][ej];
                float v = a / (1.0f + expf(-a));
                sHidE[(eg * 8 + ej) * 72 + g2 * 4 + hi] = __float2half(v);
            }
    }
    __syncthreads();

    // GEMM2 on tensor cores: R[edge][c] = hid @ W2. Warp w owns 16 edges.
    {
        wmma::fragment<wmma::matrix_a, 16, 16, 16, __half, wmma::row_major> fa[4];
#pragma unroll
        for (int kf = 0; kf < 4; kf++)
            wmma::load_matrix_sync(fa[kf], &sHidE[(w * 16) * 72 + kf * 16], 72);

#pragma unroll
        for (int nh = 0; nh < 2; nh++) {
            wmma::fragment<wmma::accumulator, 16, 16, 16, float> fc0, fc1;
            wmma::fill_fragment(fc0, 0.0f);
            wmma::fill_fragment(fc1, 0.0f);
#pragma unroll
            for (int kf = 0; kf < 4; kf++) {
                wmma::fragment<wmma::matrix_b, 16, 16, 16, __half, wmma::row_major> fb0, fb1;
                wmma::load_matrix_sync(fb0, &sW2h[kf * 16 * 72 + nh * 32], 72);
                wmma::load_matrix_sync(fb1, &sW2h[kf * 16 * 72 + nh * 32 + 16], 72);
                wmma::mma_sync(fc0, fa[kf], fb0, fc0);
                wmma::mma_sync(fc1, fa[kf], fb1, fc1);
            }
            wmma::store_matrix_sync(&U.outbuf[w][0][0],  fc0, 36, wmma::mem_row_major);
            wmma::store_matrix_sync(&U.outbuf[w][0][16], fc1, 36, wmma::mem_row_major);
            __syncwarp();

            int rrow = lane >> 1;
            int hh = lane & 1;
            const float* rowp = &U.outbuf[w][rrow][hh * 16];
            int ee = e0 + w * 16 + rrow;
            __half2* dst = (__half2*)&g_Rh[(size_t)ee * C + nh * 32 + hh * 16];
#pragma unroll
            for (int j = 0; j < 8; j++)
                dst[j] = __floats2half2_rn(rowp[2 * j], rowp[2 * j + 1]);
            __syncwarp();
        }
    }
}

// layer-0 linear with fused embedding: h = W_embed[type], h1 = h@W_up, sc = h@W_sc.
// 64 nodes/block, 4 warps, 16-node tiles (10000 % 16 == 0).
__global__ __launch_bounds__(128) void k_linear0(
    const float* __restrict__ Wup, const float* __restrict__ Wsc,
    const float* __restrict__ W_embed, const int* __restrict__ types) {
    __shared__ __align__(16) __half sWu[64 * 72];
    __shared__ __align__(16) __half sWs[64 * 72];
    __shared__ __align__(16) __half sH [64 * 72];

    int tid = threadIdx.x;
    int w = tid >> 5;
    int n0 = blockIdx.x * 64;

    for (int i = tid; i < 4096; i += 128) {
        int k = i >> 6, c = i & 63;
        sWu[k * 72 + c] = __float2half(Wup[i]);
        sWs[k * 72 + c] = __float2half(Wsc[i]);
        int n = n0 + k;
        float hv = 0.0f;
        if (n < N) hv = W_embed[types[n] * 64 + c];
        sH[k * 72 + c] = __float2half(hv);
    }
    __syncthreads();

    int nb = n0 + w * 16;
    if (nb < N) {
        wmma::fragment<wmma::matrix_a, 16, 16, 16, __half, wmma::row_major> fa[4];
#pragma unroll
        for (int kf = 0; kf < 4; kf++)
            wmma::load_matrix_sync(fa[kf], &sH[(w * 16) * 72 + kf * 16], 72);

#pragma unroll
        for (int nt = 0; nt < 4; nt++) {
            wmma::fragment<wmma::accumulator, 16, 16, 16, float> cu, cs;
            wmma::fill_fragment(cu, 0.0f);
            wmma::fill_fragment(cs, 0.0f);
#pragma unroll
            for (int kf = 0; kf < 4; kf++) {
                wmma::fragment<wmma::matrix_b, 16, 16, 16, __half, wmma::row_major> fu, fs;
                wmma::load_matrix_sync(fu, &sWu[kf * 16 * 72 + nt * 16], 72);
                wmma::load_matrix_sync(fs, &sWs[kf * 16 * 72 + nt * 16], 72);
                wmma::mma_sync(cu, fa[kf], fu, cu);
                wmma::mma_sync(cs, fa[kf], fs, cs);
            }
            wmma::store_matrix_sync(&g_h1[nb * 64 + nt * 16], cu, 64, wmma::mem_row_major);
            wmma::store_matrix_sync(&g_sc[nb * 64 + nt * 16], cs, 64, wmma::mem_row_major);
        }
    }
}

// gather: 4 nodes/block, 2 warps per node (edge-interleaved), 2 ch/thread.
// Bucket preloaded to registers; addresses via shuffles; sh rebuilt from u.
// NOTE: no min-blocks clamp — the reg squeeze to 40 caused spills (R13: L2
// 9.8->26.5%, +4.7us). 48 regs / 54% occ is the measured sweet spot.
__global__ __launch_bounds__(256) void k_gather() {
    __shared__ float sPart[4][LM][64];   // parity-1 warp partials

    int nl   = threadIdx.x >> 6;         // node slot in block (0..3)
    int n    = blockIdx.x * 4 + nl;
    int p    = (threadIdx.x >> 5) & 1;   // parity warp: edges p, p+2, ...
    int lane = threadIdx.x & 31;
    int cnt  = g_cnt[n];
    if (cnt > CAP) cnt = CAP;
    const int2* bkt = &g_bkt[(size_t)n * CAP];

    // preload bucket entries: lane i holds slots i and i+32
    int2 my0 = __ldg(&bkt[lane]);
    int2 my1 = __ldg(&bkt[lane + 32]);

    float acc0[LM], acc1[LM];
#pragma unroll
    for (int j = 0; j < LM; j++) { acc0[j] = 0.0f; acc1[j] = 0.0f; }

#pragma unroll 4
    for (int i = p; i < cnt; i += 2) {
        int src = i & 31;
        int ex = (i < 32) ? my0.x : my1.x;
        int sx = (i < 32) ? my0.y : my1.y;
        int e = __shfl_sync(0xffffffffu, ex, src);
        int s = __shfl_sync(0xffffffffu, sx, src);

        float4 u4 = __ldg(&g_u[e]);          // uniform broadcast, 16B
        float2 rv = __half22float2(*(const __half2*)&g_Rh[(size_t)e * C + 2 * lane]);
        float2 hv = *(const float2*)&g_h1[s * C + 2 * lane];

        float x = u4.x, y = u4.y, z = u4.z;
        float shv[LM] = {1.0f, x, y, z,
                         S3 * x * y, S3 * y * z,
                         0.5f * (3.0f * z * z - 1.0f), S3 * x * z,
                         0.5f * S3 * (x * x - y * y)};
        float t0 = rv.x * hv.x;
        float t1 = rv.y * hv.y;
#pragma unroll
        for (int j = 0; j < LM; j++) {
            acc0[j] = fmaf(shv[j], t0, acc0[j]);
            acc1[j] = fmaf(shv[j], t1, acc1[j]);
        }
    }

    if (p == 1) {
#pragma unroll
        for (int j = 0; j < LM; j++) {
            sPart[nl][j][2 * lane]     = acc0[j];
            sPart[nl][j][2 * lane + 1] = acc1[j];
        }
    }
    __syncthreads();
    if (p == 0) {
        float q0 = 0.0f, q1 = 0.0f;
#pragma unroll
        for (int j = 0; j < LM; j++) {
            float a0 = (acc0[j] + sPart[nl][j][2 * lane])     * INV_AVG;
            float a1 = (acc1[j] + sPart[nl][j][2 * lane + 1]) * INV_AVG;
            if (j == 0) { q0 = a0; q1 = a1; }
            q0 = fmaf(a0, a0, q0);
            q1 = fmaf(a1, a1, q1);
        }
        *(float2*)&g_q[n * C + 2 * lane] = make_float2(q0, q1);
    }
}

// Fused update(+linear of next layer): h = q@W_prod + sc (tensor cores, h kept
// in SMEM only); energy dot -> per-graph bins; if DO_LIN, h1/sc for next layer
// computed in-block (h never touches gmem). 64 nodes/block, 8 warps.
template<bool DO_LIN>
__global__ __launch_bounds__(256) void k_upd(
    const float* __restrict__ Wp, const float* __restrict__ wro,
    const int* __restrict__ batch, float* __restrict__ out,
    const float* __restrict__ Wup, const float* __restrict__ Wsc)
{
    __shared__ __align__(16) __half sWp[64 * 72];
    __shared__ __align__(16) __half sQH[64 * 72];      // q (phase U), then h (phase L)
    __shared__ __align__(16) union {
        float D[64 * 68];                               // update GEMM result
        __half Wx[2 * 64 * 72];                         // then Wup|Wsc fp16
    } A;
    __shared__ __align__(16) float sWro[64];

    int tid = threadIdx.x;
    int w = tid >> 5;
    int n0 = blockIdx.x * 64;

    for (int i = tid; i < 4096; i += 256) {
        int k = i >> 6, c = i & 63;
        sWp[k * 72 + c] = __float2half(Wp[i]);
        int n = n0 + k;
        sQH[k * 72 + c] = __float2half((n < N) ? g_q[n * 64 + c] : 0.0f);
    }
    if (tid < 64) sWro[tid] = wro[tid];
    __syncthreads();

    // Phase U: D = q @ Wp. 16 tiles (4 rows x 4 cols) over 8 warps, 2 each.
#pragma unroll
    for (int t = 0; t < 2; t++) {
        int tile = w * 2 + t;
        int tr = tile >> 2, tc = tile & 3;
        if (n0 + tr * 16 < N) {
            wmma::fragment<wmma::accumulator, 16, 16, 16, float> fc;
            wmma::fill_fragment(fc, 0.0f);
#pragma unroll
            for (int kf = 0; kf < 4; kf++) {
                wmma::fragment<wmma::matrix_a, 16, 16, 16, __half, wmma::row_major> fa;
                wmma::fragment<wmma::matrix_b, 16, 16, 16, __half, wmma::row_major> fb;
                wmma::load_matrix_sync(fa, &sQH[(tr * 16) * 72 + kf * 16], 72);
                wmma::load_matrix_sync(fb, &sWp[(kf * 16) * 72 + tc * 16], 72);
                wmma::mma_sync(fc, fa, fb, fc);
            }
            wmma::store_matrix_sync(&A.D[(tr * 16) * 68 + tc * 16], fc, 68,
                                    wmma::mem_row_major);
        }
    }
    __syncthreads();

    // Epilogue: 4 threads/node, 16 ch each: h = D + sc; energy; h -> sQH fp16
    {
        int nl = tid >> 2, qh = tid & 3;
        int n = n0 + nl;
        float part = 0.0f;
        if (n < N) {
#pragma unroll
            for (int j = 0; j < 4; j++) {
                int c = qh * 16 + j * 4;
                float4 d4 = *(const float4*)&A.D[nl * 68 + c];
                float4 s4 = *(const float4*)&g_sc[n * 64 + c];
                float h0 = d4.x + s4.x, h1v = d4.y + s4.y;
                float h2 = d4.z + s4.z, h3 = d4.w + s4.w;
                float4 w4 = *(const float4*)&sWro[c];
                part += h0 * w4.x + h1v * w4.y + h2 * w4.z + h3 * w4.w;
                if (DO_LIN) {
                    *(__half2*)&sQH[nl * 72 + c]     = __floats2half2_rn(h0, h1v);
                    *(__half2*)&sQH[nl * 72 + c + 2] = __floats2half2_rn(h2, h3);
                }
            }
        }
        part += __shfl_xor_sync(0xffffffffu, part, 1);
        part += __shfl_xor_sync(0xffffffffu, part, 2);
        if ((tid & 3) == 0 && n < N) atomicAdd(&out[batch[n]], part);
    }

    if (DO_LIN) {
        __syncthreads();   // D fully consumed; sQH now holds h
        for (int i = tid; i < 4096; i += 256) {
            int k = i >> 6, c = i & 63;
            A.Wx[k * 72 + c]           = __float2half(Wup[i]);
            A.Wx[64 * 72 + k * 72 + c] = __float2half(Wsc[i]);
        }
        __syncthreads();

        // Phase L: h1 = h@Wup, sc = h@Wsc. warp w: row = w>>1, 2 col tiles.
        int tr = w >> 1;
        if (n0 + tr * 16 < N) {
            wmma::fragment<wmma::matrix_a, 16, 16, 16, __half, wmma::row_major> fa[4];
#pragma unroll
            for (int kf = 0; kf < 4; kf++)
                wmma::load_matrix_sync(fa[kf], &sQH[(tr * 16) * 72 + kf * 16], 72);
#pragma unroll
            for (int cc = 0; cc < 2; cc++) {
                int tc = (w & 1) * 2 + cc;
                wmma::fragment<wmma::accumulator, 16, 16, 16, float> cu, cs;
                wmma::fill_fragment(cu, 0.0f);
                wmma::fill_fragment(cs, 0.0f);
#pragma unroll
                for (int kf = 0; kf < 4; kf++) {
                    wmma::fragment<wmma::matrix_b, 16, 16, 16, __half, wmma::row_major> fu, fs;
                    wmma::load_matrix_sync(fu, &A.Wx[(kf * 16) * 72 + tc * 16], 72);
                    wmma::load_matrix_sync(fs, &A.Wx[64 * 72 + (kf * 16) * 72 + tc * 16], 72);
                    wmma::mma_sync(cu, fa[kf], fu, cu);
                    wmma::mma_sync(cs, fa[kf], fs, cs);
                }
                int nb = n0 + tr * 16;
                wmma::store_matrix_sync(&g_h1[nb * 64 + tc * 16], cu, 64, wmma::mem_row_major);
                wmma::store_matrix_sync(&g_sc[nb * 64 + tc * 16], cs, 64, wmma::mem_row_major);
            }
        }
    }
}

// ---------------- launcher ----------------
extern "C" void kernel_launch(void* const* d_in, const int* in_sizes, int n_in,
                              void* d_out, int out_size) {
    const float* pos     = (const float*)d_in[0];
    const float* W_embed = (const float*)d_in[1];
    const float* W_r1    = (const float*)d_in[2];
    const float* b_r1    = (const float*)d_in[3];
    const float* W_r2    = (const float*)d_in[4];
    const float* W_up    = (const float*)d_in[5];
    const float* W_sc    = (const float*)d_in[6];
    const float* W_prod  = (const float*)d_in[7];
    const float* w_ro    = (const float*)d_in[8];
    const int*   types   = (const int*)d_in[9];
    const int*   ei      = (const int*)d_in[10];
    const int*   batch   = (const int*)d_in[11];
    float* out = (float*)d_out;

    k_prep<<<(N + 255) / 256, 256>>>(out, out_size);
    k_edge_radial<<<E / 128, 256>>>(pos, ei, W_r1, b_r1, W_r2);
    k_linear0<<<(N + 63) / 64, 128>>>(W_up, W_sc, W_embed, types);

    k_gather<<<N / 4, 256>>>();
    k_upd<true><<<(N + 63) / 64, 256>>>(W_prod, w_ro, batch, out,
                                        W_up + C * C, W_sc + C * C);
    k_gather<<<N / 4, 256>>>();
    k_upd<false><<<(N + 63) / 64, 256>>>(W_prod + C * C, w_ro + C, batch, out,
                                         nullptr, nullptr);
}

// round 15
// speedup vs baseline: 1.3789x; 1.0115x over previous
#include <cuda_runtime.h>
#include <cuda_fp16.h>
#include <mma.h>
#include <math.h>

using namespace nvcuda;

// ---------------- problem constants ----------------
namespace {
constexpr int N   = 10000;
constexpr int E   = 160000;
constexpr int C   = 64;
constexpr int LM  = 9;
constexpr int CAP = 64;          // bucket capacity (max degree ~40 for Poisson(16))
constexpr float RMAX    = 5.0f;
constexpr float INV_AVG = 1.0f / 16.0f;
constexpr float S3      = 1.7320508f;
constexpr float PI_F    = 3.14159265358979f;
constexpr float PREF    = 0.63245553203f; // sqrt(2/RMAX)
}

// ---------------- device scratch (static, no allocation) ----------------
__device__ float  g_h1[N * C];
__device__ float  g_sc[N * C];
__device__ float  g_q [N * C];
__device__ float4 g_ub[(size_t)N * CAP];        // bucket-ordered unit vectors
__device__ __half g_Rb[(size_t)N * CAP * C];    // bucket-ordered R (fp16)
__device__ int    g_send[(size_t)N * CAP];      // bucket-ordered senders
__device__ int    g_cnt[N];

// ---------------- kernels ----------------

// zero counters + output bins
__global__ void k_prep(float* __restrict__ out, int out_size) {
    int i = blockIdx.x * blockDim.x + threadIdx.x;
    if (i < N) g_cnt[i] = 0;
    if (i < out_size) out[i] = 0.0f;
}

// Fused edge kernel: geometry, bucket slot assign, radial basis, radial MLP.
// GEMM1 scalar fp32; GEMM2 on tensor cores. R/u/sender stored BUCKET-ORDERED
// (scattered stores here buy fully sequential reads in k_gather).
__global__ __launch_bounds__(256) void k_edge_radial(
    const float* __restrict__ pos, const int* __restrict__ ei,
    const float* __restrict__ W1, const float* __restrict__ b1,
    const float* __restrict__ W2)
{
    __shared__ float sW1[8 * 64];
    __shared__ float sB[64];
    __shared__ __align__(16) __half sW2h[64 * 72];    // [k][c], stride 72
    __shared__ __align__(16) __half sHidE[128 * 72];  // [edge][k], stride 72
    __shared__ int sPos[128];                         // bucket position per edge
    __shared__ __align__(16) union {
        float ef[8 * 128];            // [k][edge] radial basis (GEMM1 input)
        float outbuf[8][16][36];      // per-warp wmma staging (after GEMM1)
    } U;

    int tid = threadIdx.x;
    int lane = tid & 31;
    int w = tid >> 5;                 // warp id 0..7
    int e0 = blockIdx.x * 128;
    int el = tid & 127;
    int e = e0 + el;

    for (int i = tid; i < 512; i += 256) sW1[i] = W1[i];
    if (tid < 64) sB[tid] = b1[tid];
    for (int i = tid; i < 4096; i += 256)
        sW2h[(i >> 6) * 72 + (i & 63)] = __float2half(W2[i]);

    // geometry (computed redundantly by the 2 thread-slices; cheap)
    int s = ei[e];
    int r = ei[E + e];
    float dx = pos[r * 3 + 0] - pos[s * 3 + 0];
    float dy = pos[r * 3 + 1] - pos[s * 3 + 1];
    float dz = pos[r * 3 + 2] - pos[s * 3 + 2];
    float rr = sqrtf(dx * dx + dy * dy + dz * dz);
    float rinv = 1.0f / fmaxf(rr, 1e-9f);
    float x = dx * rinv, y = dy * rinv, z = dz * rinv;

    if (tid < 128) {
        int slot = atomicAdd(&g_cnt[r], 1);
        int p = (slot < CAP) ? (r * CAP + slot) : -1;
        sPos[el] = p;
        if (p >= 0) {
            g_ub[p] = make_float4(x, y, z, 0.0f);
            g_send[p] = s;
        }
    }

    // radial basis: 2 thread-slices x 4 sines each -> U.ef [k][edge]
    {
        float xx = rr * (1.0f / RMAX);
        float env = 0.0f;
        if (xx < 1.0f) {
            float x2 = xx * xx, x3 = x2 * xx;
            float x6 = x3 * x3, x7 = x6 * xx, x8 = x7 * xx;
            env = 1.0f - 28.0f * x6 + 48.0f * x7 - 21.0f * x8;
        }
        float wq = rr * (PI_F / RMAX);
        float pe = PREF * rinv * env;
        int j = tid >> 7;   // 0 or 1
#pragma unroll
        for (int m = 0; m < 4; m++)
            U.ef[(4 * j + m) * 128 + el] = pe * sinf((float)(4 * j + m + 1) * wq);
    }
    __syncthreads();

    int eg = tid & 15;   // edge group: 8 edges
    int g2 = tid >> 4;   // hidden quad

    // GEMM1: hid[el][h] = silu(b[h] + sum_k ef[el][k]*W1[k][h]) -> fp16 [edge][k]
    {
        float acc[4][8];
#pragma unroll
        for (int hi = 0; hi < 4; hi++) {
            float b = sB[g2 * 4 + hi];
#pragma unroll
            for (int ej = 0; ej < 8; ej++) acc[hi][ej] = b;
        }
#pragma unroll
        for (int k = 0; k < 8; k++) {
            float4 ea = *(const float4*)&U.ef[k * 128 + eg * 8];
            float4 eb = *(const float4*)&U.ef[k * 128 + eg * 8 + 4];
            float4 w4 = *(const float4*)&sW1[k * 64 + g2 * 4];
            float ee[8] = {ea.x, ea.y, ea.z, ea.w, eb.x, eb.y, eb.z, eb.w};
            float ww[4] = {w4.x, w4.y, w4.z, w4.w};
#pragma unroll
            for (int hi = 0; hi < 4; hi++)
#pragma unroll
                for (int ej = 0; ej < 8; ej++)
                    acc[hi][ej] = fmaf(ww[hi], ee[ej], acc[hi][ej]);
        }
#pragma unroll
        for (int hi = 0; hi < 4; hi++)
#pragma unroll
            for (int ej = 0; ej < 8; ej++) {
                float a = acc[hi][ej];
                float v = a / (1.0f + expf(-a));
                sHidE[(eg * 8 + ej) * 72 + g2 * 4 + hi] = __float2half(v);
            }
    }
    __syncthreads();

    // GEMM2 on tensor cores: R[edge][c] = hid @ W2, stored at bucket position.
    {
        wmma::fragment<wmma::matrix_a, 16, 16, 16, __half, wmma::row_major> fa[4];
#pragma unroll
        for (int kf = 0; kf < 4; kf++)
            wmma::load_matrix_sync(fa[kf], &sHidE[(w * 16) * 72 + kf * 16], 72);

#pragma unroll
        for (int nh = 0; nh < 2; nh++) {
            wmma::fragment<wmma::accumulator, 16, 16, 16, float> fc0, fc1;
            wmma::fill_fragment(fc0, 0.0f);
            wmma::fill_fragment(fc1, 0.0f);
#pragma unroll
            for (int kf = 0; kf < 4; kf++) {
                wmma::fragment<wmma::matrix_b, 16, 16, 16, __half, wmma::row_major> fb0, fb1;
                wmma::load_matrix_sync(fb0, &sW2h[kf * 16 * 72 + nh * 32], 72);
                wmma::load_matrix_sync(fb1, &sW2h[kf * 16 * 72 + nh * 32 + 16], 72);
                wmma::mma_sync(fc0, fa[kf], fb0, fc0);
                wmma::mma_sync(fc1, fa[kf], fb1, fc1);
            }
            wmma::store_matrix_sync(&U.outbuf[w][0][0],  fc0, 36, wmma::mem_row_major);
            wmma::store_matrix_sync(&U.outbuf[w][0][16], fc1, 36, wmma::mem_row_major);
            __syncwarp();

            int rrow = lane >> 1;
            int hh = lane & 1;
            const float* rowp = &U.outbuf[w][rrow][hh * 16];
            int p = sPos[w * 16 + rrow];
            if (p >= 0) {
                __half2* dst = (__half2*)&g_Rb[(size_t)p * C + nh * 32 + hh * 16];
#pragma unroll
                for (int j = 0; j < 8; j++)
                    dst[j] = __floats2half2_rn(rowp[2 * j], rowp[2 * j + 1]);
            }
            __syncwarp();
        }
    }
}

// layer-0 linear with fused embedding: h = W_embed[type], h1 = h@W_up, sc = h@W_sc.
// 64 nodes/block, 4 warps, 16-node tiles (10000 % 16 == 0).
__global__ __launch_bounds__(128) void k_linear0(
    const float* __restrict__ Wup, const float* __restrict__ Wsc,
    const float* __restrict__ W_embed, const int* __restrict__ types) {
    __shared__ __align__(16) __half sWu[64 * 72];
    __shared__ __align__(16) __half sWs[64 * 72];
    __shared__ __align__(16) __half sH [64 * 72];

    int tid = threadIdx.x;
    int w = tid >> 5;
    int n0 = blockIdx.x * 64;

    for (int i = tid; i < 4096; i += 128) {
        int k = i >> 6, c = i & 63;
        sWu[k * 72 + c] = __float2half(Wup[i]);
        sWs[k * 72 + c] = __float2half(Wsc[i]);
        int n = n0 + k;
        float hv = 0.0f;
        if (n < N) hv = W_embed[types[n] * 64 + c];
        sH[k * 72 + c] = __float2half(hv);
    }
    __syncthreads();

    int nb = n0 + w * 16;
    if (nb < N) {
        wmma::fragment<wmma::matrix_a, 16, 16, 16, __half, wmma::row_major> fa[4];
#pragma unroll
        for (int kf = 0; kf < 4; kf++)
            wmma::load_matrix_sync(fa[kf], &sH[(w * 16) * 72 + kf * 16], 72);

#pragma unroll
        for (int nt = 0; nt < 4; nt++) {
            wmma::fragment<wmma::accumulator, 16, 16, 16, float> cu, cs;
            wmma::fill_fragment(cu, 0.0f);
            wmma::fill_fragment(cs, 0.0f);
#pragma unroll
            for (int kf = 0; kf < 4; kf++) {
                wmma::fragment<wmma::matrix_b, 16, 16, 16, __half, wmma::row_major> fu, fs;
                wmma::load_matrix_sync(fu, &sWu[kf * 16 * 72 + nt * 16], 72);
                wmma::load_matrix_sync(fs, &sWs[kf * 16 * 72 + nt * 16], 72);
                wmma::mma_sync(cu, fa[kf], fu, cu);
                wmma::mma_sync(cs, fa[kf], fs, cs);
            }
            wmma::store_matrix_sync(&g_h1[nb * 64 + nt * 16], cu, 64, wmma::mem_row_major);
            wmma::store_matrix_sync(&g_sc[nb * 64 + nt * 16], cs, 64, wmma::mem_row_major);
        }
    }
}

// gather: 4 nodes/block, 2 warps per node (edge-interleaved), 2 ch/thread.
// ALL big reads (R, u) are now bucket-ordered -> affine in i -> streaming.
// Only h1[s] is random, and h1 (2.5MB) is L2-resident.
__global__ __launch_bounds__(256) void k_gather() {
    __shared__ float sPart[4][LM][64];   // parity-1 warp partials

    int nl   = threadIdx.x >> 6;         // node slot in block (0..3)
    int n    = blockIdx.x * 4 + nl;
    int p    = (threadIdx.x >> 5) & 1;   // parity warp: edges p, p+2, ...
    int lane = threadIdx.x & 31;
    int cnt  = g_cnt[n];
    if (cnt > CAP) cnt = CAP;
    size_t base = (size_t)n * CAP;

    // preload senders: lane i holds slots i and i+32
    int s0 = __ldg(&g_send[base + lane]);
    int s1 = __ldg(&g_send[base + lane + 32]);

    float acc0[LM], acc1[LM];
#pragma unroll
    for (int j = 0; j < LM; j++) { acc0[j] = 0.0f; acc1[j] = 0.0f; }

#pragma unroll 4
    for (int i = p; i < cnt; i += 2) {
        int s = __shfl_sync(0xffffffffu, (i < 32) ? s0 : s1, i & 31);

        float4 u4 = __ldg(&g_ub[base + i]);     // sequential broadcast
        float2 rv = __half22float2(
            *(const __half2*)&g_Rb[(base + i) * C + 2 * lane]);  // streaming
        float2 hv = *(const float2*)&g_h1[s * C + 2 * lane];     // L2-resident

        float x = u4.x, y = u4.y, z = u4.z;
        float shv[LM] = {1.0f, x, y, z,
                         S3 * x * y, S3 * y * z,
                         0.5f * (3.0f * z * z - 1.0f), S3 * x * z,
                         0.5f * S3 * (x * x - y * y)};
        float t0 = rv.x * hv.x;
        float t1 = rv.y * hv.y;
#pragma unroll
        for (int j = 0; j < LM; j++) {
            acc0[j] = fmaf(shv[j], t0, acc0[j]);
            acc1[j] = fmaf(shv[j], t1, acc1[j]);
        }
    }

    if (p == 1) {
#pragma unroll
        for (int j = 0; j < LM; j++) {
            sPart[nl][j][2 * lane]     = acc0[j];
            sPart[nl][j][2 * lane + 1] = acc1[j];
        }
    }
    __syncthreads();
    if (p == 0) {
        float q0 = 0.0f, q1 = 0.0f;
#pragma unroll
        for (int j = 0; j < LM; j++) {
            float a0 = (acc0[j] + sPart[nl][j][2 * lane])     * INV_AVG;
            float a1 = (acc1[j] + sPart[nl][j][2 * lane + 1]) * INV_AVG;
            if (j == 0) { q0 = a0; q1 = a1; }
            q0 = fmaf(a0, a0, q0);
            q1 = fmaf(a1, a1, q1);
        }
        *(float2*)&g_q[n * C + 2 * lane] = make_float2(q0, q1);
    }
}

// Fused update(+linear of next layer): h = q@W_prod + sc (tensor cores, h kept
// in SMEM only); energy dot -> per-graph bins; if DO_LIN, h1/sc for next layer
// computed in-block (h never touches gmem). 64 nodes/block, 8 warps.
template<bool DO_LIN>
__global__ __launch_bounds__(256) void k_upd(
    const float* __restrict__ Wp, const float* __restrict__ wro,
    const int* __restrict__ batch, float* __restrict__ out,
    const float* __restrict__ Wup, const float* __restrict__ Wsc)
{
    __shared__ __align__(16) __half sWp[64 * 72];
    __shared__ __align__(16) __half sQH[64 * 72];      // q (phase U), then h (phase L)
    __shared__ __align__(16) union {
        float D[64 * 68];                               // update GEMM result
        __half Wx[2 * 64 * 72];                         // then Wup|Wsc fp16
    } A;
    __shared__ __align__(16) float sWro[64];

    int tid = threadIdx.x;
    int w = tid >> 5;
    int n0 = blockIdx.x * 64;

    for (int i = tid; i < 4096; i += 256) {
        int k = i >> 6, c = i & 63;
        sWp[k * 72 + c] = __float2half(Wp[i]);
        int n = n0 + k;
        sQH[k * 72 + c] = __float2half((n < N) ? g_q[n * 64 + c] : 0.0f);
    }
    if (tid < 64) sWro[tid] = wro[tid];
    __syncthreads();

    // Phase U: D = q @ Wp. 16 tiles (4 rows x 4 cols) over 8 warps, 2 each.
#pragma unroll
    for (int t = 0; t < 2; t++) {
        int tile = w * 2 + t;
        int tr = tile >> 2, tc = tile & 3;
        if (n0 + tr * 16 < N) {
            wmma::fragment<wmma::accumulator, 16, 16, 16, float> fc;
            wmma::fill_fragment(fc, 0.0f);
#pragma unroll
            for (int kf = 0; kf < 4; kf++) {
                wmma::fragment<wmma::matrix_a, 16, 16, 16, __half, wmma::row_major> fa;
                wmma::fragment<wmma::matrix_b, 16, 16, 16, __half, wmma::row_major> fb;
                wmma::load_matrix_sync(fa, &sQH[(tr * 16) * 72 + kf * 16], 72);
                wmma::load_matrix_sync(fb, &sWp[(kf * 16) * 72 + tc * 16], 72);
                wmma::mma_sync(fc, fa, fb, fc);
            }
            wmma::store_matrix_sync(&A.D[(tr * 16) * 68 + tc * 16], fc, 68,
                                    wmma::mem_row_major);
        }
    }
    __syncthreads();

    // Epilogue: 4 threads/node, 16 ch each: h = D + sc; energy; h -> sQH fp16
    {
        int nl = tid >> 2, qh = tid & 3;
        int n = n0 + nl;
        float part = 0.0f;
        if (n < N) {
#pragma unroll
            for (int j = 0; j < 4; j++) {
                int c = qh * 16 + j * 4;
                float4 d4 = *(const float4*)&A.D[nl * 68 + c];
                float4 s4 = *(const float4*)&g_sc[n * 64 + c];
                float h0 = d4.x + s4.x, h1v = d4.y + s4.y;
                float h2 = d4.z + s4.z, h3 = d4.w + s4.w;
                float4 w4 = *(const float4*)&sWro[c];
                part += h0 * w4.x + h1v * w4.y + h2 * w4.z + h3 * w4.w;
                if (DO_LIN) {
                    *(__half2*)&sQH[nl * 72 + c]     = __floats2half2_rn(h0, h1v);
                    *(__half2*)&sQH[nl * 72 + c + 2] = __floats2half2_rn(h2, h3);
                }
            }
        }
        part += __shfl_xor_sync(0xffffffffu, part, 1);
        part += __shfl_xor_sync(0xffffffffu, part, 2);
        if ((tid & 3) == 0 && n < N) atomicAdd(&out[batch[n]], part);
    }

    if (DO_LIN) {
        __syncthreads();   // D fully consumed; sQH now holds h
        for (int i = tid; i < 4096; i += 256) {
            int k = i >> 6, c = i & 63;
            A.Wx[k * 72 + c]           = __float2half(Wup[i]);
            A.Wx[64 * 72 + k * 72 + c] = __float2half(Wsc[i]);
        }
        __syncthreads();

        // Phase L: h1 = h@Wup, sc = h@Wsc. warp w: row = w>>1, 2 col tiles.
        int tr = w >> 1;
        if (n0 + tr * 16 < N) {
            wmma::fragment<wmma::matrix_a, 16, 16, 16, __half, wmma::row_major> fa[4];
#pragma unroll
            for (int kf = 0; kf < 4; kf++)
                wmma::load_matrix_sync(fa[kf], &sQH[(tr * 16) * 72 + kf * 16], 72);
#pragma unroll
            for (int cc = 0; cc < 2; cc++) {
                int tc = (w & 1) * 2 + cc;
                wmma::fragment<wmma::accumulator, 16, 16, 16, float> cu, cs;
                wmma::fill_fragment(cu, 0.0f);
                wmma::fill_fragment(cs, 0.0f);
#pragma unroll
                for (int kf = 0; kf < 4; kf++) {
                    wmma::fragment<wmma::matrix_b, 16, 16, 16, __half, wmma::row_major> fu, fs;
                    wmma::load_matrix_sync(fu, &A.Wx[(kf * 16) * 72 + tc * 16], 72);
                    wmma::load_matrix_sync(fs, &A.Wx[64 * 72 + (kf * 16) * 72 + tc * 16], 72);
                    wmma::mma_sync(cu, fa[kf], fu, cu);
                    wmma::mma_sync(cs, fa[kf], fs, cs);
                }
                int nb = n0 + tr * 16;
                wmma::store_matrix_sync(&g_h1[nb * 64 + tc * 16], cu, 64, wmma::mem_row_major);
                wmma::store_matrix_sync(&g_sc[nb * 64 + tc * 16], cs, 64, wmma::mem_row_major);
            }
        }
    }
}

// ---------------- launcher ----------------
extern "C" void kernel_launch(void* const* d_in, const int* in_sizes, int n_in,
                              void* d_out, int out_size) {
    const float* pos     = (const float*)d_in[0];
    const float* W_embed = (const float*)d_in[1];
    const float* W_r1    = (const float*)d_in[2];
    const float* b_r1    = (const float*)d_in[3];
    const float* W_r2    = (const float*)d_in[4];
    const float* W_up    = (const float*)d_in[5];
    const float* W_sc    = (const float*)d_in[6];
    const float* W_prod  = (const float*)d_in[7];
    const float* w_ro    = (const float*)d_in[8];
    const int*   types   = (const int*)d_in[9];
    const int*   ei      = (const int*)d_in[10];
    const int*   batch   = (const int*)d_in[11];
    float* out = (float*)d_out;

    k_prep<<<(N + 255) / 256, 256>>>(out, out_size);
    k_edge_radial<<<E / 128, 256>>>(pos, ei, W_r1, b_r1, W_r2);
    k_linear0<<<(N + 63) / 64, 128>>>(W_up, W_sc, W_embed, types);

    k_gather<<<N / 4, 256>>>();
    k_upd<true><<<(N + 63) / 64, 256>>>(W_prod, w_ro, batch, out,
                                        W_up + C * C, W_sc + C * C);
    k_gather<<<N / 4, 256>>>();
    k_upd<false><<<(N + 63) / 64, 256>>>(W_prod + C * C, w_ro + C, batch, out,
                                         nullptr, nullptr);
}